// round 2
// baseline (speedup 1.0000x reference)
#include <cuda_runtime.h>

// ============================================================================
// Conv1Dfft: out = irfft( lowpass( rfft(x,131072) * conj(rfft(w,131072)) ) )
//            [:, :, :65409] + bias
// N_fft = 131072 (real) -> complex packed FFT of M = 65536 = 256 x 256
// ============================================================================

#define PI_D 3.141592653589793238462643383279502884
#define M_FFT   65536
#define KEEP    32769          // bins 0..32768 kept (== M/2+1)
#define NROWS_X 256            // 32 n * 8 c
#define NROWS_W 128            // 16 f * 8 c
#define NROWS_F 384
#define NROWS_O 512            // 32 n * 16 f
#define OUT_W   65409

// ---------------- scratch (device globals; allocation-free) ----------------
__device__ float2 g_A[NROWS_O * M_FFT];   // 268 MB ping
__device__ float2 g_B[NROWS_O * M_FFT];   // 268 MB pong
__device__ float2 g_Sx[NROWS_X * KEEP];   // x spectra (kept bins)
__device__ float2 g_Sw[NROWS_W * KEEP];   // w spectra (kept bins)
__device__ float2 g_So[NROWS_O * KEEP];   // output spectra
__device__ float2 g_twM[M_FFT];           // e^{-2pi i j / 65536}
__device__ float2 g_tw2M[M_FFT];          // e^{-2pi i j / 131072}

static __device__ __forceinline__ float2 cmul(float2 a, float2 b) {
    return make_float2(a.x * b.x - a.y * b.y, a.x * b.y + a.y * b.x);
}

// ---------------- twiddle tables (built in double, every call) -------------
__global__ void k_init_tw() {
    int i = blockIdx.x * blockDim.x + threadIdx.x;
    if (i < M_FFT) {
        double a1 = -2.0 * PI_D * (double)i / 65536.0;
        g_twM[i] = make_float2((float)cos(a1), (float)sin(a1));
        double a2 = -2.0 * PI_D * (double)i / 131072.0;
        g_tw2M[i] = make_float2((float)cos(a2), (float)sin(a2));
    }
}

// ---------------- pack real signals as complex (z[t]=x[2t]+i x[2t+1]) ------
__global__ void k_pack_x(const float2* __restrict__ x) {
    int i = blockIdx.x * blockDim.x + threadIdx.x;  // 256*32768
    if (i < NROWS_X * 32768) {
        int ro = i >> 15, t = i & 32767;
        g_A[ro * M_FFT + t] = x[i];                 // rows contiguous in x
    }
}
__global__ void k_pack_w(const float2* __restrict__ w) {
    int i = blockIdx.x * blockDim.x + threadIdx.x;  // 128*256
    if (i < NROWS_W * 256) {
        int r = i >> 8, t = i & 255;
        float2 v = make_float2(0.f, 0.f);
        if (t < 64) v = w[r * 64 + t];              // 128 real = 64 complex
        g_A[(NROWS_X + r) * M_FFT + t] = v;
    }
}

// ---------------- 256-pt radix-2 DIF FFT over one smem column --------------
// 16 threads per FFT (sub = 0..15), each does 8 butterflies/stage, 8 stages.
// Output ends bit-reversed: X[k] sits at index brev8(k).
__device__ __forceinline__ void fft256_cols(float2 (*tile)[17],
                                            const float2* tw, int sub, int c) {
    #pragma unroll
    for (int h = 128, ts = 1; h >= 1; h >>= 1, ts <<= 1) {
        #pragma unroll
        for (int u = 0; u < 8; u++) {
            int j   = sub * 8 + u;
            int pos = j & (h - 1);
            int ia  = ((j & ~(h - 1)) << 1) | pos;
            int ib  = ia + h;
            float2 a = tile[ia][c], b = tile[ib][c];
            tile[ia][c] = make_float2(a.x + b.x, a.y + b.y);
            float2 d = make_float2(a.x - b.x, a.y - b.y);
            tile[ib][c] = cmul(d, tw[pos * ts]);
        }
        __syncthreads();
    }
}

// ---------------- pass 1: FFT over t1 (stride 256) + inter twiddle ---------
// reads g_A, writes g_B.  nz_t1: nonzero t1 blocks (zero-pad skip).
__global__ __launch_bounds__(256) void k_fft_pass1(int row0, int nz_t1) {
    __shared__ float2 tile[256][17];
    __shared__ float2 tw[128];
    int row = row0 + blockIdx.y;
    int t2b = blockIdx.x * 16;
    int tid = threadIdx.x;
    int c = tid & 15, sub = tid >> 4;
    if (tid < 128) tw[tid] = g_twM[tid << 8];       // e^{-2pi i t/256}
    const float2* src = g_A + (size_t)row * M_FFT;
    #pragma unroll
    for (int it = 0; it < 16; it++) {
        int t1 = it * 16 + sub;
        tile[t1][c] = (t1 < nz_t1) ? src[t1 * 256 + t2b + c]
                                   : make_float2(0.f, 0.f);
    }
    __syncthreads();
    fft256_cols(tile, tw, sub, c);
    float2* dst = g_B + (size_t)row * M_FFT;
    int t2 = t2b + c;
    #pragma unroll
    for (int it = 0; it < 16; it++) {
        int k1 = it * 16 + sub;
        float2 v = tile[__brev((unsigned)k1) >> 24][c];
        float2 w = g_twM[(k1 * t2) & (M_FFT - 1)];  // e^{-2pi i t2 k1 / 65536}
        dst[k1 * 256 + t2] = cmul(v, w);
    }
}

// ---------------- pass 2: FFT over t2 (contiguous), natural-order out ------
// reads g_B, writes g_A.  Z[k1 + 256*k2].
__global__ __launch_bounds__(256) void k_fft_pass2(int row0) {
    __shared__ float2 tile[256][17];
    __shared__ float2 tw[128];
    int row = row0 + blockIdx.y;
    int k1b = blockIdx.x * 16;
    int tid = threadIdx.x;
    int c = tid & 15, sub = tid >> 4;
    if (tid < 128) tw[tid] = g_twM[tid << 8];
    const float2* src = g_B + (size_t)row * M_FFT + k1b * 256;
    #pragma unroll
    for (int it = 0; it < 16; it++) {
        int e = it * 256 + tid;                     // fully coalesced
        tile[e & 255][e >> 8] = src[e];
    }
    __syncthreads();
    fft256_cols(tile, tw, sub, c);
    float2* dst = g_A + (size_t)row * M_FFT;
    #pragma unroll
    for (int it = 0; it < 16; it++) {
        int k2 = it * 16 + sub;
        dst[k2 * 256 + k1b + c] = tile[__brev((unsigned)k2) >> 24][c];
    }
}

// ---------------- Hermitian unpack: Z (packed) -> rfft bins 0..32768 -------
// X[k] = 0.5(Zk + conj(Zm)) - 0.5 i e^{-i pi k/M} (Zk - conj(Zm)), Zm=Z[M-k]
__global__ void k_unpack() {
    int i = blockIdx.x * blockDim.x + threadIdx.x;
    if (i >= NROWS_F * KEEP) return;
    int ro = i / KEEP;
    int k  = i - ro * KEEP;
    const float2* zr = g_A + (size_t)ro * M_FFT;
    float2 zk = zr[k];
    float2 zm = zr[(M_FFT - k) & (M_FFT - 1)];
    float2 E = make_float2(0.5f * (zk.x + zm.x), 0.5f * (zk.y - zm.y));
    float2 D = make_float2(zk.x - zm.x, zk.y + zm.y);
    float2 TD = cmul(g_tw2M[k], D);
    float2 X = make_float2(E.x + 0.5f * TD.y, E.y - 0.5f * TD.x);
    if (ro < NROWS_X) g_Sx[ro * KEEP + k] = X;
    else              g_Sw[(ro - NROWS_X) * KEEP + k] = X;
}

// ---------------- einsum over c: So[n,f,k] = sum_c Sx[n,c,k] conj(Sw[f,c,k])
#define KT 8
__global__ __launch_bounds__(256) void k_einsum() {
    __shared__ float2 Xs[NROWS_X][KT];
    __shared__ float2 Ws[NROWS_W][KT];
    int k0 = blockIdx.x * KT;
    int tid = threadIdx.x;
    for (int idx = tid; idx < NROWS_X * KT; idx += 256) {
        int r = idx >> 3, kk = idx & 7, kg = k0 + kk;
        Xs[r][kk] = (kg < KEEP) ? g_Sx[r * KEEP + kg] : make_float2(0.f, 0.f);
    }
    for (int idx = tid; idx < NROWS_W * KT; idx += 256) {
        int r = idx >> 3, kk = idx & 7, kg = k0 + kk;
        Ws[r][kk] = (kg < KEEP) ? g_Sw[r * KEEP + kg] : make_float2(0.f, 0.f);
    }
    __syncthreads();
    for (int o = tid; o < NROWS_O * KT; o += 256) {
        int kk = o & 7, nf = o >> 3;
        int n = nf >> 4, f = nf & 15;
        float2 acc = make_float2(0.f, 0.f);
        #pragma unroll
        for (int cc = 0; cc < 8; cc++) {
            float2 a = Xs[n * 8 + cc][kk];
            float2 b = Ws[f * 8 + cc][kk];
            acc.x += a.x * b.x + a.y * b.y;   // a * conj(b)
            acc.y += a.y * b.x - a.x * b.y;
        }
        int kg = k0 + kk;
        if (kg < KEEP) g_So[(size_t)nf * KEEP + kg] = acc;
    }
}

// ---------------- inverse pack: spectrum -> packed complex (conj, /M) ------
// E = 0.5(Sk+conj(Sm)); O = 0.5 e^{+i pi k/M}(Sk-conj(Sm)); Zi = E + iO
// store conj(Zi)/M, then forward-FFT, then conj in final kernel = IFFT.
__global__ void k_invpack() {
    int i = blockIdx.x * blockDim.x + threadIdx.x;
    if (i >= NROWS_O * M_FFT) return;
    int ro = i >> 16, k = i & (M_FFT - 1);
    const float inv = 1.0f / 65536.0f;
    const float2* sr = g_So + (size_t)ro * KEEP;
    float2 Sk = (k <= 32768) ? sr[k] : make_float2(0.f, 0.f);
    float2 Sm = (k >= 32768) ? sr[M_FFT - k] : make_float2(0.f, 0.f);
    float2 E = make_float2(0.5f * (Sk.x + Sm.x), 0.5f * (Sk.y - Sm.y));
    float2 D = make_float2(Sk.x - Sm.x, Sk.y + Sm.y);
    float2 T = g_tw2M[k];
    float2 Tc = make_float2(T.x, -T.y);             // e^{+i pi k/M}
    float2 O = cmul(Tc, D);                          // = 2*O
    float Ox = 0.5f * O.x, Oy = 0.5f * O.y;
    // Zi = (E.x - Oy, E.y + Ox); write conj(Zi) * inv
    g_A[i] = make_float2((E.x - Oy) * inv, -(E.y + Ox) * inv);
}

// ---------------- final: de-pack real output, add bias ---------------------
__global__ void k_final(float* __restrict__ out, const float* __restrict__ bias) {
    int i = blockIdx.x * blockDim.x + threadIdx.x;
    const int total = NROWS_O * OUT_W;
    if (i >= total) return;
    int rf = i / OUT_W;
    int t  = i - rf * OUT_W;
    int f  = rf & 15;
    int m  = t >> 1;
    float2 z = g_A[(size_t)rf * M_FFT + m];          // z[m] = conj(FFT result)
    float v = (t & 1) ? -z.y : z.x;
    out[i] = v + bias[f];
}

// ============================================================================
extern "C" void kernel_launch(void* const* d_in, const int* in_sizes, int n_in,
                              void* d_out, int out_size) {
    const float2* x    = (const float2*)d_in[0];
    const float2* w    = (const float2*)d_in[1];
    const float*  bias = (const float*)d_in[2];
    float* out = (float*)d_out;

    k_init_tw<<<(M_FFT + 255) / 256, 256>>>();

    // pack
    k_pack_x<<<(NROWS_X * 32768 + 255) / 256, 256>>>(x);
    k_pack_w<<<(NROWS_W * 256 + 255) / 256, 256>>>(w);

    // forward FFTs (x rows: half the time samples nonzero; w rows: 1 block)
    { dim3 g(16, NROWS_X); k_fft_pass1<<<g, 256>>>(0, 128); }
    { dim3 g(16, NROWS_W); k_fft_pass1<<<g, 256>>>(NROWS_X, 1); }
    { dim3 g(16, NROWS_F); k_fft_pass2<<<g, 256>>>(0); }

    // unpack to rfft bins 0..32768 (== the kept bins)
    k_unpack<<<(NROWS_F * KEEP + 255) / 256, 256>>>();

    // pointwise complex contraction over c
    k_einsum<<<(KEEP + KT - 1) / KT, 256>>>();

    // inverse rfft (conj-FFT-conj), 512 rows
    k_invpack<<<(NROWS_O * M_FFT + 255) / 256, 256>>>();
    { dim3 g(16, NROWS_O); k_fft_pass1<<<g, 256>>>(0, 256); }
    { dim3 g(16, NROWS_O); k_fft_pass2<<<g, 256>>>(0); }

    // final de-pack + bias
    k_final<<<(NROWS_O * OUT_W + 255) / 256, 256>>>(out, bias);
}

// round 3
// speedup vs baseline: 2.6341x; 2.6341x over previous
#include <cuda_runtime.h>

// ============================================================================
// Conv1Dfft via packed-real four-step FFT (M = 65536 = 256 x 256),
// register-resident 16x16 FFT per 256-pt transform, heavy fusion.
// ============================================================================

#define PI_D 3.141592653589793238462643383279502884
#define M_FFT   65536
#define KEEP    32769          // bins 0..32768 kept (== M/2+1)
#define NROWS_X 256            // 32 n * 8 c
#define NROWS_W 128            // 16 f * 8 c
#define NROWS_F 384
#define NROWS_O 512            // 32 n * 16 f
#define OUT_W   65409

#define MODE_X   0
#define MODE_W   1
#define MODE_INV 2

// ---------------- scratch (device globals; allocation-free) ----------------
__device__ float2 g_A[(size_t)NROWS_O * M_FFT];   // pong (fwd pass2 out)
__device__ float2 g_B[(size_t)NROWS_O * M_FFT];   // ping (pass1 out)
__device__ float2 g_So[(size_t)NROWS_O * KEEP];   // output spectra
__device__ float2 g_twM[M_FFT];                   // e^{-2pi i j / 65536}
__device__ float2 g_tw2M[M_FFT];                  // e^{-2pi i j / 131072}

static __device__ __forceinline__ float2 cmul(float2 a, float2 b) {
    return make_float2(a.x * b.x - a.y * b.y, a.x * b.y + a.y * b.x);
}

// ---------------- twiddle tables ------------------------------------------
__global__ void k_init_tw() {
    int i = blockIdx.x * blockDim.x + threadIdx.x;
    if (i < M_FFT) {
        double a1 = -2.0 * PI_D * (double)i / 65536.0;
        g_twM[i] = make_float2((float)cos(a1), (float)sin(a1));
        double a2 = -2.0 * PI_D * (double)i / 131072.0;
        g_tw2M[i] = make_float2((float)cos(a2), (float)sin(a2));
    }
}

// ---------------- 16-pt DFT in registers (radix-4 x radix-4) ---------------
// natural-order in/out: r_out[k] = sum_j r_in[j] e^{-2pi i jk/16}
__device__ __forceinline__ void fft16(float2 r[16]) {
    const float C1 = 0.9238795325112867f;   // cos(pi/8)
    const float S1 = 0.3826834323650898f;   // sin(pi/8)
    const float R2 = 0.7071067811865476f;
    float2 t[16];
    // stage 1: DFT4 over a1 (stride 4) for each a0; twiddle w16^{a0*p1};
    // store t[a0 + 4*p1]
    #pragma unroll
    for (int a0 = 0; a0 < 4; a0++) {
        float2 x0 = r[a0], x1 = r[a0 + 4], x2 = r[a0 + 8], x3 = r[a0 + 12];
        float2 s0 = make_float2(x0.x + x2.x, x0.y + x2.y);
        float2 d0 = make_float2(x0.x - x2.x, x0.y - x2.y);
        float2 s1 = make_float2(x1.x + x3.x, x1.y + x3.y);
        float2 d1 = make_float2(x1.x - x3.x, x1.y - x3.y);
        float2 y0 = make_float2(s0.x + s1.x, s0.y + s1.y);
        float2 y2 = make_float2(s0.x - s1.x, s0.y - s1.y);
        float2 y1 = make_float2(d0.x + d1.y, d0.y - d1.x);   // d0 - i*d1
        float2 y3 = make_float2(d0.x - d1.y, d0.y + d1.x);   // d0 + i*d1
        if (a0 == 0) {
            t[0] = y0; t[4] = y1; t[8] = y2; t[12] = y3;
        } else if (a0 == 1) {
            t[1]  = y0;
            t[5]  = cmul(y1, make_float2( C1, -S1));   // w16^1
            t[9]  = cmul(y2, make_float2( R2, -R2));   // w16^2
            t[13] = cmul(y3, make_float2( S1, -C1));   // w16^3
        } else if (a0 == 2) {
            t[2]  = y0;
            t[6]  = cmul(y1, make_float2( R2, -R2));   // w16^2
            t[10] = make_float2( y2.y, -y2.x);          // * w16^4 = -i
            t[14] = cmul(y3, make_float2(-R2, -R2));   // w16^6
        } else {
            t[3]  = y0;
            t[7]  = cmul(y1, make_float2( S1, -C1));   // w16^3
            t[11] = cmul(y2, make_float2(-R2, -R2));   // w16^6
            t[15] = cmul(y3, make_float2(-C1,  S1));   // w16^9
        }
    }
    // stage 2: DFT4 over a0 (contiguous in group p1); out r[4*p0 + p1]
    #pragma unroll
    for (int p1 = 0; p1 < 4; p1++) {
        float2 x0 = t[4 * p1], x1 = t[4 * p1 + 1];
        float2 x2 = t[4 * p1 + 2], x3 = t[4 * p1 + 3];
        float2 s0 = make_float2(x0.x + x2.x, x0.y + x2.y);
        float2 d0 = make_float2(x0.x - x2.x, x0.y - x2.y);
        float2 s1 = make_float2(x1.x + x3.x, x1.y + x3.y);
        float2 d1 = make_float2(x1.x - x3.x, x1.y - x3.y);
        r[p1]      = make_float2(s0.x + s1.x, s0.y + s1.y);
        r[8 + p1]  = make_float2(s0.x - s1.x, s0.y - s1.y);
        r[4 + p1]  = make_float2(d0.x + d1.y, d0.y - d1.x);
        r[12 + p1] = make_float2(d0.x - d1.y, d0.y + d1.x);
    }
}

// swizzled smem slot for element (u, c):  (u<<4) | (c ^ (u & 15))
#define SMIDX(u, c) (((u) << 4) | ((c) ^ ((u) & 15)))

// ---------------- pass 1: 256-pt FFT over t1 (z[256*t1 + t2]) --------------
// + inter twiddle w65536^{k1*t2}; writes g_B[row][k1*256 + t2].
// Loads fused per MODE (x input / w input / inverse spectrum pack).
template <int MODE>
__global__ __launch_bounds__(256) void k_pass1(const float2* __restrict__ src,
                                               int row0) {
    __shared__ float2 sm[4096];
    __shared__ float2 tw256[256];
    int tid = threadIdx.x;
    int c = tid & 15, s = tid >> 4;          // s = b (load/step1), then p'
    int t2 = blockIdx.x * 16 + c;
    int row = row0 + blockIdx.y;
    tw256[tid] = g_twM[tid << 8];            // w256^j

    float2 r[16];                            // r[a] = z[256*(16a+s) + t2]
    if (MODE == MODE_X) {
        const float2* xr = src + (size_t)row * 32768;
        #pragma unroll
        for (int a = 0; a < 16; a++)
            r[a] = (a < 8) ? xr[(a * 16 + s) * 256 + t2]
                           : make_float2(0.f, 0.f);
    } else if (MODE == MODE_W) {
        #pragma unroll
        for (int a = 0; a < 16; a++) r[a] = make_float2(0.f, 0.f);
        if (s == 0 && t2 < 64)
            r[0] = src[(size_t)blockIdx.y * 64 + t2];
    } else {  // MODE_INV: packed-inverse input from g_So (conj trick, /M)
        const float2* sr = g_So + (size_t)row * KEEP;
        const float inv = 1.0f / 65536.0f;
        #pragma unroll
        for (int a = 0; a < 16; a++) {
            int k = (a * 16 + s) * 256 + t2;
            float2 Sk = (k <= 32768) ? sr[k] : make_float2(0.f, 0.f);
            float2 Sm = (k >= 32768) ? sr[M_FFT - k] : make_float2(0.f, 0.f);
            float2 E = make_float2(0.5f * (Sk.x + Sm.x), 0.5f * (Sk.y - Sm.y));
            float2 D = make_float2(Sk.x - Sm.x, Sk.y + Sm.y);
            float2 T = g_tw2M[k];
            float2 O = cmul(make_float2(T.x, -T.y), D);  // e^{+i pi k/M} * D
            r[a] = make_float2((E.x - 0.5f * O.y) * inv,
                               -(E.y + 0.5f * O.x) * inv);
        }
    }
    __syncthreads();                         // tw256 ready

    fft16(r);                                // r[p] = A_s[p]
    #pragma unroll
    for (int p = 0; p < 16; p++) {           // twiddle w256^{s*p}, transpose
        int u = p * 16 + s;                  // u & 15 == s
        sm[SMIDX(u, c)] = cmul(r[p], tw256[s * p]);
    }
    __syncthreads();
    #pragma unroll
    for (int b = 0; b < 16; b++) {           // gather row p' = s
        int u = s * 16 + b;
        r[b] = sm[SMIDX(u, c)];
    }
    fft16(r);                                // r[q] = X[16q + s]  (k1)

    // inter twiddle w65536^{k1*t2} via 2 loads + recurrence
    float2 cur = g_twM[(s * t2) & (M_FFT - 1)];
    float2 stp = g_twM[(t2 << 4) & (M_FFT - 1)];
    float2* dst = g_B + (size_t)row * M_FFT;
    #pragma unroll
    for (int q = 0; q < 16; q++) {
        int k1 = q * 16 + s;
        dst[k1 * 256 + t2] = cmul(r[q], cur);
        cur = cmul(cur, stp);
    }
}

// ---------------- pass 2: 256-pt FFT over t2, natural-order output ---------
// FINAL=0: writes g_A[row][k2*256 + k1] (for einsum).
// FINAL=1: writes real output + bias directly (inverse depack fused).
template <int FINAL>
__global__ __launch_bounds__(256) void k_pass2(float* __restrict__ out,
                                               const float* __restrict__ bias,
                                               int row0) {
    __shared__ float2 sm[4096];
    __shared__ float2 tw256[256];
    int tid = threadIdx.x;
    int c = tid & 15, s = tid >> 4;
    int row = row0 + blockIdx.y;
    int k1b = blockIdx.x * 16;
    tw256[tid] = g_twM[tid << 8];

    // coalesced staging: element (k1 = k1b+cc, t2 = u) at src[cc*256 + u]
    const float2* src = g_B + (size_t)row * M_FFT + (size_t)k1b * 256;
    #pragma unroll
    for (int it = 0; it < 16; it++)
        sm[SMIDX(tid, it)] = src[it * 256 + tid];   // u = tid, c = it
    __syncthreads();

    float2 r[16];
    #pragma unroll
    for (int a = 0; a < 16; a++) {
        int u = a * 16 + s;
        r[a] = sm[SMIDX(u, c)];
    }
    fft16(r);
    __syncthreads();
    #pragma unroll
    for (int p = 0; p < 16; p++) {
        int u = p * 16 + s;
        sm[SMIDX(u, c)] = cmul(r[p], tw256[s * p]);
    }
    __syncthreads();
    #pragma unroll
    for (int b = 0; b < 16; b++) {
        int u = s * 16 + b;
        r[b] = sm[SMIDX(u, c)];
    }
    fft16(r);                                // r[q] = X[16q + s]  (k2)

    if (!FINAL) {
        float2* dst = g_A + (size_t)row * M_FFT;
        #pragma unroll
        for (int q = 0; q < 16; q++)
            dst[(q * 16 + s) * 256 + k1b + c] = r[q];
    } else {
        float bv = bias[row & 15];
        float* orow = out + (size_t)row * OUT_W;
        #pragma unroll
        for (int q = 0; q < 16; q++) {
            int m = (q * 16 + s) * 256 + k1b + c;   // packed time index
            int t = 2 * m;
            if (t < OUT_W)     orow[t]     =  r[q].x + bv;
            if (t + 1 < OUT_W) orow[t + 1] = -r[q].y + bv;
        }
    }
}

// ---------------- einsum over c with Hermitian unpack fused ----------------
// X[r][k] = unpack(Z[r][k], Z[r][M-k]);  So[n,f,k] = sum_c X[n,c,k] conj(X_w[f,c,k])
#define KT 8
__global__ __launch_bounds__(256) void k_einsum() {
    __shared__ float2 Xs[NROWS_X][KT];
    __shared__ float2 Ws[NROWS_W][KT];
    int k0 = blockIdx.x * KT;
    int tid = threadIdx.x;
    for (int idx = tid; idx < NROWS_F * KT; idx += 256) {
        int r = idx >> 3, kk = idx & 7;
        int kg = k0 + kk;
        float2 X = make_float2(0.f, 0.f);
        if (kg < KEEP) {
            const float2* zr = g_A + (size_t)r * M_FFT;
            float2 zk = zr[kg];
            float2 zm = zr[(M_FFT - kg) & (M_FFT - 1)];
            float2 E = make_float2(0.5f * (zk.x + zm.x), 0.5f * (zk.y - zm.y));
            float2 D = make_float2(zk.x - zm.x, zk.y + zm.y);
            float2 TD = cmul(g_tw2M[kg], D);
            X = make_float2(E.x + 0.5f * TD.y, E.y - 0.5f * TD.x);
        }
        if (r < NROWS_X) Xs[r][kk] = X;
        else             Ws[r - NROWS_X][kk] = X;
    }
    __syncthreads();
    for (int o = tid; o < NROWS_O * KT; o += 256) {
        int kk = o & 7, nf = o >> 3;
        int n = nf >> 4, f = nf & 15;
        float2 acc = make_float2(0.f, 0.f);
        #pragma unroll
        for (int cc = 0; cc < 8; cc++) {
            float2 a = Xs[n * 8 + cc][kk];
            float2 b = Ws[f * 8 + cc][kk];
            acc.x += a.x * b.x + a.y * b.y;   // a * conj(b)
            acc.y += a.y * b.x - a.x * b.y;
        }
        int kg = k0 + kk;
        if (kg < KEEP) g_So[(size_t)nf * KEEP + kg] = acc;
    }
}

// ============================================================================
extern "C" void kernel_launch(void* const* d_in, const int* in_sizes, int n_in,
                              void* d_out, int out_size) {
    const float2* x    = (const float2*)d_in[0];
    const float2* w    = (const float2*)d_in[1];
    const float*  bias = (const float*)d_in[2];
    float* out = (float*)d_out;

    k_init_tw<<<(M_FFT + 255) / 256, 256>>>();

    // forward: pass1 with fused packing
    { dim3 g(16, NROWS_X); k_pass1<MODE_X><<<g, 256>>>(x, 0); }
    { dim3 g(16, NROWS_W); k_pass1<MODE_W><<<g, 256>>>(w, NROWS_X); }
    { dim3 g(16, NROWS_F); k_pass2<0><<<g, 256>>>(nullptr, nullptr, 0); }

    // pointwise contraction over c (Hermitian unpack fused into loads)
    k_einsum<<<(KEEP + KT - 1) / KT, 256>>>();

    // inverse: pass1 with fused inverse-pack, pass2 with fused depack+bias
    { dim3 g(16, NROWS_O); k_pass1<MODE_INV><<<g, 256>>>(nullptr, 0); }
    { dim3 g(16, NROWS_O); k_pass2<1><<<g, 256>>>(out, bias, 0); }
}

// round 5
// speedup vs baseline: 2.8226x; 1.0716x over previous
#include <cuda_runtime.h>
#include <cuda_fp16.h>

// ============================================================================
// Conv1Dfft via packed-real four-step FFT (M = 65536 = 256 x 256),
// register-resident 16x16 FFT, heavy fusion, fp16 complex intermediates.
// ============================================================================

#define PI_D 3.141592653589793238462643383279502884
#define M_FFT   65536
#define KEEP    32769          // bins 0..32768 kept (== M/2+1)
#define NROWS_X 256            // 32 n * 8 c
#define NROWS_W 128            // 16 f * 8 c
#define NROWS_F 384
#define NROWS_O 512            // 32 n * 16 f
#define OUT_W   65409

#define MODE_X   0
#define MODE_W   1
#define MODE_INV 2

// ---------------- scratch (device globals; allocation-free) ----------------
__device__ __half2 g_A[(size_t)NROWS_F * M_FFT];   // fwd pass2 out (spectra Z)
__device__ __half2 g_B[(size_t)NROWS_O * M_FFT];   // pass1 out (both directions)
__device__ __half2 g_So[(size_t)NROWS_O * KEEP];   // product spectra
__device__ float2 g_twM[M_FFT];                    // e^{-2pi i j / 65536}
__device__ float2 g_tw2M[M_FFT];                   // e^{-2pi i j / 131072}

static __device__ __forceinline__ float2 cmul(float2 a, float2 b) {
    return make_float2(a.x * b.x - a.y * b.y, a.x * b.y + a.y * b.x);
}
static __device__ __forceinline__ float2 ldc(const __half2* p) {
    return __half22float2(*p);
}
static __device__ __forceinline__ void stc(__half2* p, float2 v) {
    *p = __float22half2_rn(v);
}

// ---------------- twiddle tables ------------------------------------------
__global__ void k_init_tw() {
    int i = blockIdx.x * blockDim.x + threadIdx.x;
    if (i < M_FFT) {
        double a1 = -2.0 * PI_D * (double)i / 65536.0;
        g_twM[i] = make_float2((float)cos(a1), (float)sin(a1));
        double a2 = -2.0 * PI_D * (double)i / 131072.0;
        g_tw2M[i] = make_float2((float)cos(a2), (float)sin(a2));
    }
}

// ---------------- 16-pt DFT in registers (radix-4 x radix-4) ---------------
__device__ __forceinline__ void fft16(float2 r[16]) {
    const float C1 = 0.9238795325112867f;
    const float S1 = 0.3826834323650898f;
    const float R2 = 0.7071067811865476f;
    float2 t[16];
    #pragma unroll
    for (int a0 = 0; a0 < 4; a0++) {
        float2 x0 = r[a0], x1 = r[a0 + 4], x2 = r[a0 + 8], x3 = r[a0 + 12];
        float2 s0 = make_float2(x0.x + x2.x, x0.y + x2.y);
        float2 d0 = make_float2(x0.x - x2.x, x0.y - x2.y);
        float2 s1 = make_float2(x1.x + x3.x, x1.y + x3.y);
        float2 d1 = make_float2(x1.x - x3.x, x1.y - x3.y);
        float2 y0 = make_float2(s0.x + s1.x, s0.y + s1.y);
        float2 y2 = make_float2(s0.x - s1.x, s0.y - s1.y);
        float2 y1 = make_float2(d0.x + d1.y, d0.y - d1.x);
        float2 y3 = make_float2(d0.x - d1.y, d0.y + d1.x);
        if (a0 == 0) {
            t[0] = y0; t[4] = y1; t[8] = y2; t[12] = y3;
        } else if (a0 == 1) {
            t[1]  = y0;
            t[5]  = cmul(y1, make_float2( C1, -S1));
            t[9]  = cmul(y2, make_float2( R2, -R2));
            t[13] = cmul(y3, make_float2( S1, -C1));
        } else if (a0 == 2) {
            t[2]  = y0;
            t[6]  = cmul(y1, make_float2( R2, -R2));
            t[10] = make_float2( y2.y, -y2.x);
            t[14] = cmul(y3, make_float2(-R2, -R2));
        } else {
            t[3]  = y0;
            t[7]  = cmul(y1, make_float2( S1, -C1));
            t[11] = cmul(y2, make_float2(-R2, -R2));
            t[15] = cmul(y3, make_float2(-C1,  S1));
        }
    }
    #pragma unroll
    for (int p1 = 0; p1 < 4; p1++) {
        float2 x0 = t[4 * p1], x1 = t[4 * p1 + 1];
        float2 x2 = t[4 * p1 + 2], x3 = t[4 * p1 + 3];
        float2 s0 = make_float2(x0.x + x2.x, x0.y + x2.y);
        float2 d0 = make_float2(x0.x - x2.x, x0.y - x2.y);
        float2 s1 = make_float2(x1.x + x3.x, x1.y + x3.y);
        float2 d1 = make_float2(x1.x - x3.x, x1.y - x3.y);
        r[p1]      = make_float2(s0.x + s1.x, s0.y + s1.y);
        r[8 + p1]  = make_float2(s0.x - s1.x, s0.y - s1.y);
        r[4 + p1]  = make_float2(d0.x + d1.y, d0.y - d1.x);
        r[12 + p1] = make_float2(d0.x - d1.y, d0.y + d1.x);
    }
}

// swizzled smem slot for element (u, c):  (u<<4) | (c ^ (u & 15))
#define SMIDX(u, c) (((u) << 4) | ((c) ^ ((u) & 15)))

// ---------------- pass 1: 256-pt FFT over t1 + inter twiddle ---------------
template <int MODE>
__global__ __launch_bounds__(256) void k_pass1(const float2* __restrict__ src,
                                               int row0) {
    __shared__ float2 sm[4096];
    __shared__ float2 tw256[256];
    int tid = threadIdx.x;
    int c = tid & 15, s = tid >> 4;
    int t2 = blockIdx.x * 16 + c;
    int row = row0 + blockIdx.y;
    tw256[tid] = g_twM[tid << 8];

    float2 r[16];
    if (MODE == MODE_X) {
        const float2* xr = src + (size_t)row * 32768;
        #pragma unroll
        for (int a = 0; a < 16; a++)
            r[a] = (a < 8) ? xr[(a * 16 + s) * 256 + t2]
                           : make_float2(0.f, 0.f);
    } else if (MODE == MODE_W) {
        #pragma unroll
        for (int a = 0; a < 16; a++) r[a] = make_float2(0.f, 0.f);
        if (s == 0 && t2 < 64)
            r[0] = src[(size_t)blockIdx.y * 64 + t2];
    } else {  // MODE_INV: packed-inverse input from g_So (conj trick, /M)
        const __half2* sr = g_So + (size_t)row * KEEP;
        const float inv = 1.0f / 65536.0f;
        #pragma unroll
        for (int a = 0; a < 16; a++) {
            int k = (a * 16 + s) * 256 + t2;
            float2 Sk = (k <= 32768) ? ldc(sr + k) : make_float2(0.f, 0.f);
            float2 Sm = (k >= 32768) ? ldc(sr + (M_FFT - k))
                                     : make_float2(0.f, 0.f);
            float2 E = make_float2(0.5f * (Sk.x + Sm.x), 0.5f * (Sk.y - Sm.y));
            float2 D = make_float2(Sk.x - Sm.x, Sk.y + Sm.y);
            float2 T = g_tw2M[k];
            float2 O = cmul(make_float2(T.x, -T.y), D);
            r[a] = make_float2((E.x - 0.5f * O.y) * inv,
                               -(E.y + 0.5f * O.x) * inv);
        }
    }
    __syncthreads();

    fft16(r);
    #pragma unroll
    for (int p = 0; p < 16; p++) {
        int u = p * 16 + s;
        sm[SMIDX(u, c)] = cmul(r[p], tw256[s * p]);
    }
    __syncthreads();
    #pragma unroll
    for (int b = 0; b < 16; b++) {
        int u = s * 16 + b;
        r[b] = sm[SMIDX(u, c)];
    }
    fft16(r);                                // r[q] = X[16q + s]  (k1)

    float2 cur = g_twM[(s * t2) & (M_FFT - 1)];
    float2 stp = g_twM[(t2 << 4) & (M_FFT - 1)];
    __half2* dst = g_B + (size_t)row * M_FFT;
    #pragma unroll
    for (int q = 0; q < 16; q++) {
        int k1 = q * 16 + s;
        stc(dst + k1 * 256 + t2, cmul(r[q], cur));
        cur = cmul(cur, stp);
    }
}

// ---------------- pass 2: 256-pt FFT over t2, natural-order output ---------
template <int FINAL>
__global__ __launch_bounds__(256) void k_pass2(float* __restrict__ out,
                                               const float* __restrict__ bias,
                                               int row0) {
    __shared__ float2 sm[4096];
    __shared__ float2 tw256[256];
    int tid = threadIdx.x;
    int c = tid & 15, s = tid >> 4;
    int row = row0 + blockIdx.y;
    int k1b = blockIdx.x * 16;
    tw256[tid] = g_twM[tid << 8];

    const __half2* src = g_B + (size_t)row * M_FFT + (size_t)k1b * 256;
    #pragma unroll
    for (int it = 0; it < 16; it++)
        sm[SMIDX(tid, it)] = ldc(src + it * 256 + tid);
    __syncthreads();

    float2 r[16];
    #pragma unroll
    for (int a = 0; a < 16; a++) {
        int u = a * 16 + s;
        r[a] = sm[SMIDX(u, c)];
    }
    fft16(r);
    __syncthreads();
    #pragma unroll
    for (int p = 0; p < 16; p++) {
        int u = p * 16 + s;
        sm[SMIDX(u, c)] = cmul(r[p], tw256[s * p]);
    }
    __syncthreads();
    #pragma unroll
    for (int b = 0; b < 16; b++) {
        int u = s * 16 + b;
        r[b] = sm[SMIDX(u, c)];
    }
    fft16(r);                                // r[q] = X[16q + s]  (k2)

    if (!FINAL) {
        __half2* dst = g_A + (size_t)row * M_FFT;
        #pragma unroll
        for (int q = 0; q < 16; q++)
            stc(dst + (q * 16 + s) * 256 + k1b + c, r[q]);
    } else {
        float bv = bias[row & 15];
        float* orow = out + (size_t)row * OUT_W;
        #pragma unroll
        for (int q = 0; q < 16; q++) {
            int m = (q * 16 + s) * 256 + k1b + c;   // packed time index
            int t = 2 * m;
            // scalar stores: row base is only 4B-aligned (OUT_W odd)
            if (t < OUT_W)     orow[t]     =  r[q].x + bv;
            if (t + 1 < OUT_W) orow[t + 1] = -r[q].y + bv;
        }
    }
}

// ---------------- einsum over c with Hermitian unpack fused ----------------
#define KT 8
__global__ __launch_bounds__(256) void k_einsum() {
    __shared__ float2 Xs[NROWS_X][KT];
    __shared__ float2 Ws[NROWS_W][KT];
    int k0 = blockIdx.x * KT;
    int tid = threadIdx.x;
    for (int idx = tid; idx < NROWS_F * KT; idx += 256) {
        int r = idx >> 3, kk = idx & 7;
        int kg = k0 + kk;
        float2 X = make_float2(0.f, 0.f);
        if (kg < KEEP) {
            const __half2* zr = g_A + (size_t)r * M_FFT;
            float2 zk = ldc(zr + kg);
            float2 zm = ldc(zr + ((M_FFT - kg) & (M_FFT - 1)));
            float2 E = make_float2(0.5f * (zk.x + zm.x), 0.5f * (zk.y - zm.y));
            float2 D = make_float2(zk.x - zm.x, zk.y + zm.y);
            float2 TD = cmul(g_tw2M[kg], D);
            X = make_float2(E.x + 0.5f * TD.y, E.y - 0.5f * TD.x);
        }
        if (r < NROWS_X) Xs[r][kk] = X;
        else             Ws[r - NROWS_X][kk] = X;
    }
    __syncthreads();
    for (int o = tid; o < NROWS_O * KT; o += 256) {
        int kk = o & 7, nf = o >> 3;
        int n = nf >> 4, f = nf & 15;
        float2 acc = make_float2(0.f, 0.f);
        #pragma unroll
        for (int cc = 0; cc < 8; cc++) {
            float2 a = Xs[n * 8 + cc][kk];
            float2 b = Ws[f * 8 + cc][kk];
            acc.x += a.x * b.x + a.y * b.y;   // a * conj(b)
            acc.y += a.y * b.x - a.x * b.y;
        }
        int kg = k0 + kk;
        if (kg < KEEP) stc(g_So + (size_t)nf * KEEP + kg, acc);
    }
}

// ============================================================================
extern "C" void kernel_launch(void* const* d_in, const int* in_sizes, int n_in,
                              void* d_out, int out_size) {
    const float2* x    = (const float2*)d_in[0];
    const float2* w    = (const float2*)d_in[1];
    const float*  bias = (const float*)d_in[2];
    float* out = (float*)d_out;

    k_init_tw<<<(M_FFT + 255) / 256, 256>>>();

    // forward: pass1 with fused packing
    { dim3 g(16, NROWS_X); k_pass1<MODE_X><<<g, 256>>>(x, 0); }
    { dim3 g(16, NROWS_W); k_pass1<MODE_W><<<g, 256>>>(w, NROWS_X); }
    { dim3 g(16, NROWS_F); k_pass2<0><<<g, 256>>>(nullptr, nullptr, 0); }

    // pointwise contraction over c (Hermitian unpack fused into loads)
    k_einsum<<<(KEEP + KT - 1) / KT, 256>>>();

    // inverse: pass1 with fused inverse-pack, pass2 with fused depack+bias
    { dim3 g(16, NROWS_O); k_pass1<MODE_INV><<<g, 256>>>(nullptr, 0); }
    { dim3 g(16, NROWS_O); k_pass2<1><<<g, 256>>>(out, bias, 0); }
}

// round 6
// speedup vs baseline: 2.8942x; 1.0253x over previous
#include <cuda_runtime.h>
#include <cuda_fp16.h>

// ============================================================================
// Conv1Dfft via packed-real four-step FFT (M = 65536 = 256 x 256),
// register-resident 16x16 FFT, fp16 global intermediates, f32x2 packed math.
// ============================================================================

#define PI_D 3.141592653589793238462643383279502884
#define M_FFT   65536
#define KEEP    32769          // bins 0..32768 kept (== M/2+1)
#define NROWS_X 256            // 32 n * 8 c
#define NROWS_W 128            // 16 f * 8 c
#define NROWS_F 384
#define NROWS_O 512            // 32 n * 16 f
#define OUT_W   65409

// ---------------- scratch (device globals; allocation-free) ----------------
__device__ __half2 g_A[(size_t)NROWS_F * M_FFT];   // fwd pass2 out (spectra Z)
__device__ __half2 g_B[(size_t)NROWS_O * M_FFT];   // pass1 out (both directions)
__device__ __half2 g_So[(size_t)NROWS_O * KEEP];   // product spectra
__device__ float2 g_twM[M_FFT];                    // e^{-2pi i j / 65536}
__device__ float2 g_tw2M[M_FFT];                   // e^{-2pi i j / 131072}

// ---------------- packed f32x2 complex helpers -----------------------------
static __device__ __forceinline__ float2 padd(float2 a, float2 b) {
    unsigned long long ua, ub, ur;
    asm("mov.b64 %0, {%1,%2};" : "=l"(ua) : "f"(a.x), "f"(a.y));
    asm("mov.b64 %0, {%1,%2};" : "=l"(ub) : "f"(b.x), "f"(b.y));
    asm("add.rn.f32x2 %0, %1, %2;" : "=l"(ur) : "l"(ua), "l"(ub));
    float2 o;
    asm("mov.b64 {%0,%1}, %2;" : "=f"(o.x), "=f"(o.y) : "l"(ur));
    return o;
}
static __device__ __forceinline__ float2 psub(float2 a, float2 b) {
    // a - b  ==  fma(b, (-1,-1), a)
    unsigned long long ua, ub, ur;
    const unsigned long long NEG1 = 0xBF800000BF800000ULL;  // (-1.f, -1.f)
    asm("mov.b64 %0, {%1,%2};" : "=l"(ua) : "f"(a.x), "f"(a.y));
    asm("mov.b64 %0, {%1,%2};" : "=l"(ub) : "f"(b.x), "f"(b.y));
    asm("fma.rn.f32x2 %0, %1, %2, %3;" : "=l"(ur) : "l"(ub), "l"(NEG1), "l"(ua));
    float2 o;
    asm("mov.b64 {%0,%1}, %2;" : "=f"(o.x), "=f"(o.y) : "l"(ur));
    return o;
}
static __device__ __forceinline__ float2 cmul(float2 a, float2 b) {
    return make_float2(fmaf(a.x, b.x, -(a.y * b.y)),
                       fmaf(a.x, b.y,   a.y * b.x));
}
static __device__ __forceinline__ float2 ldc(const __half2* p) {
    return __half22float2(*p);
}
static __device__ __forceinline__ void stc(__half2* p, float2 v) {
    *p = __float22half2_rn(v);
}

// ---------------- twiddle tables ------------------------------------------
__global__ void k_init_tw() {
    int i = blockIdx.x * blockDim.x + threadIdx.x;
    if (i < M_FFT) {
        double a1 = -2.0 * PI_D * (double)i / 65536.0;
        g_twM[i] = make_float2((float)cos(a1), (float)sin(a1));
        double a2 = -2.0 * PI_D * (double)i / 131072.0;
        g_tw2M[i] = make_float2((float)cos(a2), (float)sin(a2));
    }
}

// ---------------- 4-pt DFT on packed complex -------------------------------
// y0..y3 = DFT4(x0..x3) (decimation-in-frequency order: y[k]=sum x[j] w4^{jk})
static __device__ __forceinline__ void dft4(float2 x0, float2 x1, float2 x2,
                                            float2 x3, float2& y0, float2& y1,
                                            float2& y2, float2& y3) {
    float2 s0 = padd(x0, x2);
    float2 d0 = psub(x0, x2);
    float2 s1 = padd(x1, x3);
    float2 d1 = psub(x1, x3);
    y0 = padd(s0, s1);
    y2 = psub(s0, s1);
    float2 sw = make_float2(d1.y, -d1.x);   // -i*d1
    y1 = padd(d0, sw);                       // d0 - i d1
    y3 = psub(d0, sw);                       // d0 + i d1
}

// ---------------- 16-pt DFT in registers (radix-4 x radix-4) ---------------
__device__ __forceinline__ void fft16(float2 r[16]) {
    const float C1 = 0.9238795325112867f;
    const float S1 = 0.3826834323650898f;
    const float R2 = 0.7071067811865476f;
    float2 t[16];
    {   // a0 = 0
        float2 y0, y1, y2, y3;
        dft4(r[0], r[4], r[8], r[12], y0, y1, y2, y3);
        t[0] = y0; t[4] = y1; t[8] = y2; t[12] = y3;
    }
    {   // a0 = 1
        float2 y0, y1, y2, y3;
        dft4(r[1], r[5], r[9], r[13], y0, y1, y2, y3);
        t[1]  = y0;
        t[5]  = cmul(y1, make_float2( C1, -S1));
        t[9]  = cmul(y2, make_float2( R2, -R2));
        t[13] = cmul(y3, make_float2( S1, -C1));
    }
    {   // a0 = 2
        float2 y0, y1, y2, y3;
        dft4(r[2], r[6], r[10], r[14], y0, y1, y2, y3);
        t[2]  = y0;
        t[6]  = cmul(y1, make_float2( R2, -R2));
        t[10] = make_float2( y2.y, -y2.x);
        t[14] = cmul(y3, make_float2(-R2, -R2));
    }
    {   // a0 = 3
        float2 y0, y1, y2, y3;
        dft4(r[3], r[7], r[11], r[15], y0, y1, y2, y3);
        t[3]  = y0;
        t[7]  = cmul(y1, make_float2( S1, -C1));
        t[11] = cmul(y2, make_float2(-R2, -R2));
        t[15] = cmul(y3, make_float2(-C1,  S1));
    }
    #pragma unroll
    for (int p1 = 0; p1 < 4; p1++) {
        float2 y0, y1, y2, y3;
        dft4(t[4 * p1], t[4 * p1 + 1], t[4 * p1 + 2], t[4 * p1 + 3],
             y0, y1, y2, y3);
        r[p1] = y0; r[4 + p1] = y1; r[8 + p1] = y2; r[12 + p1] = y3;
    }
}

// swizzled smem slot for element (u, c):  (u<<4) | (c ^ (u & 15))
#define SMIDX(u, c) (((u) << 4) | ((c) ^ ((u) & 15)))

// ---------------- pass 1: 256-pt FFT over t1 + inter twiddle ---------------
// FWD=1: rows [0,256) from x, rows [256,384) from w.  FWD=0: inverse from g_So.
template <int FWD>
__global__ __launch_bounds__(256) void k_pass1(const float2* __restrict__ x,
                                               const float2* __restrict__ w) {
    __shared__ float2 sm[4096];
    __shared__ float2 tw256[256];
    int tid = threadIdx.x;
    int c = tid & 15, s = tid >> 4;
    int t2 = blockIdx.x * 16 + c;
    int row = blockIdx.y;
    tw256[tid] = g_twM[tid << 8];

    float2 r[16];
    if (FWD) {
        if (row < NROWS_X) {
            const float2* xr = x + (size_t)row * 32768;
            #pragma unroll
            for (int a = 0; a < 16; a++)
                r[a] = (a < 8) ? xr[(a * 16 + s) * 256 + t2]
                               : make_float2(0.f, 0.f);
        } else {
            #pragma unroll
            for (int a = 0; a < 16; a++) r[a] = make_float2(0.f, 0.f);
            if (s == 0 && t2 < 64)
                r[0] = w[(size_t)(row - NROWS_X) * 64 + t2];
        }
    } else {  // inverse: packed-inverse input from g_So (conj trick, /M)
        const __half2* sr = g_So + (size_t)row * KEEP;
        const float inv = 1.0f / 65536.0f;
        #pragma unroll
        for (int a = 0; a < 16; a++) {
            int k = (a * 16 + s) * 256 + t2;
            float2 Sk = (k <= 32768) ? ldc(sr + k) : make_float2(0.f, 0.f);
            float2 Sm = (k >= 32768) ? ldc(sr + (M_FFT - k))
                                     : make_float2(0.f, 0.f);
            float2 E = make_float2(0.5f * (Sk.x + Sm.x), 0.5f * (Sk.y - Sm.y));
            float2 D = make_float2(Sk.x - Sm.x, Sk.y + Sm.y);
            float2 T = g_tw2M[k];
            float2 O = cmul(make_float2(T.x, -T.y), D);
            r[a] = make_float2((E.x - 0.5f * O.y) * inv,
                               -(E.y + 0.5f * O.x) * inv);
        }
    }
    __syncthreads();

    fft16(r);
    #pragma unroll
    for (int p = 0; p < 16; p++) {
        int u = p * 16 + s;
        sm[SMIDX(u, c)] = cmul(r[p], tw256[s * p]);
    }
    __syncthreads();
    #pragma unroll
    for (int b = 0; b < 16; b++) {
        int u = s * 16 + b;
        r[b] = sm[SMIDX(u, c)];
    }
    fft16(r);                                // r[q] = X[16q + s]  (k1)

    float2 cur = g_twM[(s * t2) & (M_FFT - 1)];
    float2 stp = g_twM[(t2 << 4) & (M_FFT - 1)];
    __half2* dst = g_B + (size_t)row * M_FFT;
    #pragma unroll
    for (int q = 0; q < 16; q++) {
        int k1 = q * 16 + s;
        stc(dst + k1 * 256 + t2, cmul(r[q], cur));
        cur = cmul(cur, stp);
    }
}

// ---------------- pass 2: 256-pt FFT over t2, natural-order output ---------
template <int FINAL>
__global__ __launch_bounds__(256) void k_pass2(float* __restrict__ out,
                                               const float* __restrict__ bias) {
    __shared__ float2 sm[4096];
    __shared__ float2 tw256[256];
    int tid = threadIdx.x;
    int c = tid & 15, s = tid >> 4;
    int row = blockIdx.y;
    int k1b = blockIdx.x * 16;
    tw256[tid] = g_twM[tid << 8];

    const __half2* src = g_B + (size_t)row * M_FFT + (size_t)k1b * 256;
    #pragma unroll
    for (int it = 0; it < 16; it++)
        sm[SMIDX(tid, it)] = ldc(src + it * 256 + tid);
    __syncthreads();

    float2 r[16];
    #pragma unroll
    for (int a = 0; a < 16; a++) {
        int u = a * 16 + s;
        r[a] = sm[SMIDX(u, c)];
    }
    fft16(r);
    __syncthreads();
    #pragma unroll
    for (int p = 0; p < 16; p++) {
        int u = p * 16 + s;
        sm[SMIDX(u, c)] = cmul(r[p], tw256[s * p]);
    }
    __syncthreads();
    #pragma unroll
    for (int b = 0; b < 16; b++) {
        int u = s * 16 + b;
        r[b] = sm[SMIDX(u, c)];
    }
    fft16(r);                                // r[q] = X[16q + s]  (k2)

    if (!FINAL) {
        __half2* dst = g_A + (size_t)row * M_FFT;
        #pragma unroll
        for (int q = 0; q < 16; q++)
            stc(dst + (q * 16 + s) * 256 + k1b + c, r[q]);
    } else {
        float bv = bias[row & 15];
        float* orow = out + (size_t)row * OUT_W;
        #pragma unroll
        for (int q = 0; q < 16; q++) {
            int m = (q * 16 + s) * 256 + k1b + c;   // packed time index
            int t = 2 * m;
            // scalar stores: row base is only 4B-aligned (OUT_W odd)
            if (t < OUT_W)     orow[t]     =  r[q].x + bv;
            if (t + 1 < OUT_W) orow[t + 1] = -r[q].y + bv;
        }
    }
}

// ---------------- einsum over c with Hermitian unpack fused ----------------
#define KT 8
__global__ __launch_bounds__(256) void k_einsum() {
    __shared__ float2 Xs[NROWS_X][KT];
    __shared__ float2 Ws[NROWS_W][KT];
    int k0 = blockIdx.x * KT;
    int tid = threadIdx.x;
    for (int idx = tid; idx < NROWS_F * KT; idx += 256) {
        int r = idx >> 3, kk = idx & 7;
        int kg = k0 + kk;
        float2 X = make_float2(0.f, 0.f);
        if (kg < KEEP) {
            const __half2* zr = g_A + (size_t)r * M_FFT;
            float2 zk = ldc(zr + kg);
            float2 zm = ldc(zr + ((M_FFT - kg) & (M_FFT - 1)));
            float2 E = make_float2(0.5f * (zk.x + zm.x), 0.5f * (zk.y - zm.y));
            float2 D = make_float2(zk.x - zm.x, zk.y + zm.y);
            float2 TD = cmul(g_tw2M[kg], D);
            X = make_float2(E.x + 0.5f * TD.y, E.y - 0.5f * TD.x);
        }
        if (r < NROWS_X) Xs[r][kk] = X;
        else             Ws[r - NROWS_X][kk] = X;
    }
    __syncthreads();
    for (int o = tid; o < NROWS_O * KT; o += 256) {
        int kk = o & 7, nf = o >> 3;
        int n = nf >> 4, f = nf & 15;
        float2 acc = make_float2(0.f, 0.f);
        #pragma unroll
        for (int cc = 0; cc < 8; cc++) {
            float2 a = Xs[n * 8 + cc][kk];
            float2 b = Ws[f * 8 + cc][kk];
            acc.x += a.x * b.x + a.y * b.y;   // a * conj(b)
            acc.y += a.y * b.x - a.x * b.y;
        }
        int kg = k0 + kk;
        if (kg < KEEP) stc(g_So + (size_t)nf * KEEP + kg, acc);
    }
}

// ============================================================================
extern "C" void kernel_launch(void* const* d_in, const int* in_sizes, int n_in,
                              void* d_out, int out_size) {
    const float2* x    = (const float2*)d_in[0];
    const float2* w    = (const float2*)d_in[1];
    const float*  bias = (const float*)d_in[2];
    float* out = (float*)d_out;

    k_init_tw<<<(M_FFT + 255) / 256, 256>>>();

    // forward: pass1 (x rows + w rows in one launch), pass2
    { dim3 g(16, NROWS_F); k_pass1<1><<<g, 256>>>(x, w); }
    { dim3 g(16, NROWS_F); k_pass2<0><<<g, 256>>>(nullptr, nullptr); }

    // pointwise contraction over c (Hermitian unpack fused into loads)
    k_einsum<<<(KEEP + KT - 1) / KT, 256>>>();

    // inverse: pass1 with fused inverse-pack, pass2 with fused depack+bias
    { dim3 g(16, NROWS_O); k_pass1<0><<<g, 256>>>(nullptr, nullptr); }
    { dim3 g(16, NROWS_O); k_pass2<1><<<g, 256>>>(out, bias); }
}

// round 7
// speedup vs baseline: 3.0178x; 1.0427x over previous
#include <cuda_runtime.h>
#include <cuda_fp16.h>

// ============================================================================
// Conv1Dfft via packed-real four-step FFT (M = 65536 = 256 x 256),
// register 16x16 FFT, fp16 global + fp16 smem intermediates, f32x2 math.
// ============================================================================

#define PI_D 3.141592653589793238462643383279502884
#define M_FFT   65536
#define KEEP    32769          // bins 0..32768 kept (== M/2+1)
#define NROWS_X 256            // 32 n * 8 c
#define NROWS_W 128            // 16 f * 8 c
#define NROWS_F 384
#define NROWS_O 512            // 32 n * 16 f
#define OUT_W   65409

// ---------------- scratch (device globals; allocation-free) ----------------
__device__ __half2 g_A[(size_t)NROWS_F * M_FFT];   // fwd pass2 out (spectra Z)
__device__ __half2 g_B[(size_t)NROWS_O * M_FFT];   // pass1 out (both directions)
__device__ __half2 g_So[(size_t)NROWS_O * KEEP];   // product spectra
__device__ float2 g_twM[M_FFT];                    // e^{-2pi i j / 65536}
__device__ float2 g_tw2M[M_FFT];                   // e^{-2pi i j / 131072}

// ---------------- packed f32x2 complex helpers -----------------------------
static __device__ __forceinline__ float2 padd(float2 a, float2 b) {
    unsigned long long ua, ub, ur;
    asm("mov.b64 %0, {%1,%2};" : "=l"(ua) : "f"(a.x), "f"(a.y));
    asm("mov.b64 %0, {%1,%2};" : "=l"(ub) : "f"(b.x), "f"(b.y));
    asm("add.rn.f32x2 %0, %1, %2;" : "=l"(ur) : "l"(ua), "l"(ub));
    float2 o;
    asm("mov.b64 {%0,%1}, %2;" : "=f"(o.x), "=f"(o.y) : "l"(ur));
    return o;
}
static __device__ __forceinline__ float2 psub(float2 a, float2 b) {
    unsigned long long ua, ub, ur;
    const unsigned long long NEG1 = 0xBF800000BF800000ULL;  // (-1.f, -1.f)
    asm("mov.b64 %0, {%1,%2};" : "=l"(ua) : "f"(a.x), "f"(a.y));
    asm("mov.b64 %0, {%1,%2};" : "=l"(ub) : "f"(b.x), "f"(b.y));
    asm("fma.rn.f32x2 %0, %1, %2, %3;" : "=l"(ur) : "l"(ub), "l"(NEG1), "l"(ua));
    float2 o;
    asm("mov.b64 {%0,%1}, %2;" : "=f"(o.x), "=f"(o.y) : "l"(ur));
    return o;
}
static __device__ __forceinline__ float2 cmul(float2 a, float2 b) {
    return make_float2(fmaf(a.x, b.x, -(a.y * b.y)),
                       fmaf(a.x, b.y,   a.y * b.x));
}
static __device__ __forceinline__ float2 ldc(const __half2* p) {
    return __half22float2(*p);
}
static __device__ __forceinline__ void stc(__half2* p, float2 v) {
    *p = __float22half2_rn(v);
}

// ---------------- twiddle tables ------------------------------------------
__global__ void k_init_tw() {
    int i = blockIdx.x * blockDim.x + threadIdx.x;
    if (i < M_FFT) {
        double a1 = -2.0 * PI_D * (double)i / 65536.0;
        g_twM[i] = make_float2((float)cos(a1), (float)sin(a1));
        double a2 = -2.0 * PI_D * (double)i / 131072.0;
        g_tw2M[i] = make_float2((float)cos(a2), (float)sin(a2));
    }
}

// ---------------- 4-pt DFT on packed complex -------------------------------
static __device__ __forceinline__ void dft4(float2 x0, float2 x1, float2 x2,
                                            float2 x3, float2& y0, float2& y1,
                                            float2& y2, float2& y3) {
    float2 s0 = padd(x0, x2);
    float2 d0 = psub(x0, x2);
    float2 s1 = padd(x1, x3);
    float2 d1 = psub(x1, x3);
    y0 = padd(s0, s1);
    y2 = psub(s0, s1);
    float2 sw = make_float2(d1.y, -d1.x);   // -i*d1
    y1 = padd(d0, sw);
    y3 = psub(d0, sw);
}

// ---------------- 16-pt DFT in registers (radix-4 x radix-4) ---------------
__device__ __forceinline__ void fft16(float2 r[16]) {
    const float C1 = 0.9238795325112867f;
    const float S1 = 0.3826834323650898f;
    const float R2 = 0.7071067811865476f;
    float2 t[16];
    {
        float2 y0, y1, y2, y3;
        dft4(r[0], r[4], r[8], r[12], y0, y1, y2, y3);
        t[0] = y0; t[4] = y1; t[8] = y2; t[12] = y3;
    }
    {
        float2 y0, y1, y2, y3;
        dft4(r[1], r[5], r[9], r[13], y0, y1, y2, y3);
        t[1]  = y0;
        t[5]  = cmul(y1, make_float2( C1, -S1));
        t[9]  = cmul(y2, make_float2( R2, -R2));
        t[13] = cmul(y3, make_float2( S1, -C1));
    }
    {
        float2 y0, y1, y2, y3;
        dft4(r[2], r[6], r[10], r[14], y0, y1, y2, y3);
        t[2]  = y0;
        t[6]  = cmul(y1, make_float2( R2, -R2));
        t[10] = make_float2( y2.y, -y2.x);
        t[14] = cmul(y3, make_float2(-R2, -R2));
    }
    {
        float2 y0, y1, y2, y3;
        dft4(r[3], r[7], r[11], r[15], y0, y1, y2, y3);
        t[3]  = y0;
        t[7]  = cmul(y1, make_float2( S1, -C1));
        t[11] = cmul(y2, make_float2(-R2, -R2));
        t[15] = cmul(y3, make_float2(-C1,  S1));
    }
    #pragma unroll
    for (int p1 = 0; p1 < 4; p1++) {
        float2 y0, y1, y2, y3;
        dft4(t[4 * p1], t[4 * p1 + 1], t[4 * p1 + 2], t[4 * p1 + 3],
             y0, y1, y2, y3);
        r[p1] = y0; r[4 + p1] = y1; r[8 + p1] = y2; r[12 + p1] = y3;
    }
}

// pad-17 smem slot: bank-conflict-free for the (u = a*16+s, c) access shapes
#define SMI(u, c) ((u) * 17 + (c))

// ---------------- pass 1: 256-pt FFT over t1 + inter twiddle ---------------
// FWD=1: rows [0,256) from x, rows [256,384) from w.  FWD=0: inverse from g_So.
template <int FWD>
__global__ __launch_bounds__(256) void k_pass1(const float2* __restrict__ x,
                                               const float2* __restrict__ w) {
    __shared__ __half2 sm[4352];
    __shared__ float2 tw256[256];
    int tid = threadIdx.x;
    int c = tid & 15, s = tid >> 4;
    int t2 = blockIdx.x * 16 + c;
    int row = blockIdx.y;
    tw256[tid] = g_twM[tid << 8];

    float2 r[16];
    if (FWD) {
        if (row < NROWS_X) {
            const float2* xr = x + (size_t)row * 32768;
            #pragma unroll
            for (int a = 0; a < 16; a++)
                r[a] = (a < 8) ? xr[(a * 16 + s) * 256 + t2]
                               : make_float2(0.f, 0.f);
        } else {
            #pragma unroll
            for (int a = 0; a < 16; a++) r[a] = make_float2(0.f, 0.f);
            if (s == 0 && t2 < 64)
                r[0] = w[(size_t)(row - NROWS_X) * 64 + t2];
        }
    } else {  // inverse: packed-inverse input from g_So (conj trick, /M)
        const __half2* sr = g_So + (size_t)row * KEEP;
        const float inv = 1.0f / 65536.0f;
        #pragma unroll
        for (int a = 0; a < 16; a++) {
            int k = (a * 16 + s) * 256 + t2;
            float2 Sk = (k <= 32768) ? ldc(sr + k) : make_float2(0.f, 0.f);
            float2 Sm = (k >= 32768) ? ldc(sr + (M_FFT - k))
                                     : make_float2(0.f, 0.f);
            float2 E = make_float2(0.5f * (Sk.x + Sm.x), 0.5f * (Sk.y - Sm.y));
            float2 D = make_float2(Sk.x - Sm.x, Sk.y + Sm.y);
            float2 T = g_tw2M[k];
            float2 O = cmul(make_float2(T.x, -T.y), D);
            r[a] = make_float2((E.x - 0.5f * O.y) * inv,
                               -(E.y + 0.5f * O.x) * inv);
        }
    }
    __syncthreads();

    fft16(r);
    #pragma unroll
    for (int p = 0; p < 16; p++)
        stc(&sm[SMI(p * 16 + s, c)], cmul(r[p], tw256[s * p]));
    __syncthreads();
    #pragma unroll
    for (int b = 0; b < 16; b++)
        r[b] = ldc(&sm[SMI(s * 16 + b, c)]);
    fft16(r);                                // r[q] = X[16q + s]  (k1)

    float2 cur = g_twM[(s * t2) & (M_FFT - 1)];
    float2 stp = g_twM[(t2 << 4) & (M_FFT - 1)];
    __half2* dst = g_B + (size_t)row * M_FFT;
    #pragma unroll
    for (int q = 0; q < 16; q++) {
        int k1 = q * 16 + s;
        stc(dst + k1 * 256 + t2, cmul(r[q], cur));
        cur = cmul(cur, stp);
    }
}

// ---------------- pass 2: 256-pt FFT over t2, natural-order output ---------
template <int FINAL>
__global__ __launch_bounds__(256) void k_pass2(float* __restrict__ out,
                                               const float* __restrict__ bias) {
    __shared__ __half2 sm[4352];
    __shared__ float2 tw256[256];
    int tid = threadIdx.x;
    int c = tid & 15, s = tid >> 4;
    int row = blockIdx.y;
    int k1b = blockIdx.x * 16;
    tw256[tid] = g_twM[tid << 8];

    // coalesced staging: raw half2 copy (no conversion, no extra rounding)
    const __half2* src = g_B + (size_t)row * M_FFT + (size_t)k1b * 256;
    #pragma unroll
    for (int it = 0; it < 16; it++)
        sm[SMI(tid, it)] = src[it * 256 + tid];
    __syncthreads();

    float2 r[16];
    #pragma unroll
    for (int a = 0; a < 16; a++)
        r[a] = ldc(&sm[SMI(a * 16 + s, c)]);
    fft16(r);
    __syncthreads();
    #pragma unroll
    for (int p = 0; p < 16; p++)
        stc(&sm[SMI(p * 16 + s, c)], cmul(r[p], tw256[s * p]));
    __syncthreads();
    #pragma unroll
    for (int b = 0; b < 16; b++)
        r[b] = ldc(&sm[SMI(s * 16 + b, c)]);
    fft16(r);                                // r[q] = X[16q + s]  (k2)

    if (!FINAL) {
        __half2* dst = g_A + (size_t)row * M_FFT;
        #pragma unroll
        for (int q = 0; q < 16; q++)
            stc(dst + (q * 16 + s) * 256 + k1b + c, r[q]);
    } else {
        float bv = bias[row & 15];
        float* orow = out + (size_t)row * OUT_W;
        #pragma unroll
        for (int q = 0; q < 16; q++) {
            int m = (q * 16 + s) * 256 + k1b + c;   // packed time index
            int t = 2 * m;
            // scalar stores: row base is only 4B-aligned (OUT_W odd)
            if (t < OUT_W)     orow[t]     =  r[q].x + bv;
            if (t + 1 < OUT_W) orow[t + 1] = -r[q].y + bv;
        }
    }
}

// ---------------- einsum over c (register-blocked, packed FMA) -------------
// thread (n, kk): X[n, c, kk] in registers (pre-packed), loop f over smem W.
#define KT 8
__global__ __launch_bounds__(256) void k_einsum() {
    __shared__ float2 Xs[NROWS_X][KT];
    __shared__ float2 Ws[NROWS_W][KT];
    int k0 = blockIdx.x * KT;
    int tid = threadIdx.x;
    // load + Hermitian unpack
    for (int idx = tid; idx < NROWS_F * KT; idx += 256) {
        int r = idx >> 3, kk2 = idx & 7;
        int kg2 = k0 + kk2;
        float2 X = make_float2(0.f, 0.f);
        if (kg2 < KEEP) {
            const __half2* zr = g_A + (size_t)r * M_FFT;
            float2 zk = ldc(zr + kg2);
            float2 zm = ldc(zr + ((M_FFT - kg2) & (M_FFT - 1)));
            float2 E = make_float2(0.5f * (zk.x + zm.x), 0.5f * (zk.y - zm.y));
            float2 D = make_float2(zk.x - zm.x, zk.y + zm.y);
            float2 TD = cmul(g_tw2M[kg2], D);
            X = make_float2(E.x + 0.5f * TD.y, E.y - 0.5f * TD.x);
        }
        if (r < NROWS_X) Xs[r][kk2] = X;
        else             Ws[r - NROWS_X][kk2] = X;
    }
    __syncthreads();

    int kk = tid & 7, n = tid >> 3;          // n in 0..31
    int kg = k0 + kk;
    // pre-pack X row: pa1 = (a.x, a.y), pa2 = (a.y, -a.x)
    unsigned long long pa1[8], pa2[8];
    #pragma unroll
    for (int cc = 0; cc < 8; cc++) {
        float2 a = Xs[n * 8 + cc][kk];
        float nax = -a.x;
        asm("mov.b64 %0, {%1,%2};" : "=l"(pa1[cc]) : "f"(a.x), "f"(a.y));
        asm("mov.b64 %0, {%1,%2};" : "=l"(pa2[cc]) : "f"(a.y), "f"(nax));
    }
    #pragma unroll
    for (int f = 0; f < 16; f++) {
        unsigned long long acc0 = 0, acc1 = 0;
        #pragma unroll
        for (int cc = 0; cc < 8; cc++) {
            float2 b = Ws[f * 8 + cc][kk];
            unsigned long long pbx, pby;
            asm("mov.b64 %0, {%1,%1};" : "=l"(pbx) : "f"(b.x));
            asm("mov.b64 %0, {%1,%1};" : "=l"(pby) : "f"(b.y));
            asm("fma.rn.f32x2 %0, %1, %2, %0;" : "+l"(acc0)
                : "l"(pa1[cc]), "l"(pbx));
            asm("fma.rn.f32x2 %0, %1, %2, %0;" : "+l"(acc1)
                : "l"(pa2[cc]), "l"(pby));
        }
        unsigned long long accs;
        asm("add.rn.f32x2 %0, %1, %2;" : "=l"(accs) : "l"(acc0), "l"(acc1));
        float2 o;
        asm("mov.b64 {%0,%1}, %2;" : "=f"(o.x), "=f"(o.y) : "l"(accs));
        if (kg < KEEP)
            stc(g_So + (size_t)(n * 16 + f) * KEEP + kg, o);
    }
}

// ============================================================================
extern "C" void kernel_launch(void* const* d_in, const int* in_sizes, int n_in,
                              void* d_out, int out_size) {
    const float2* x    = (const float2*)d_in[0];
    const float2* w    = (const float2*)d_in[1];
    const float*  bias = (const float*)d_in[2];
    float* out = (float*)d_out;

    k_init_tw<<<(M_FFT + 255) / 256, 256>>>();

    // forward: pass1 (x rows + w rows in one launch), pass2
    { dim3 g(16, NROWS_F); k_pass1<1><<<g, 256>>>(x, w); }
    { dim3 g(16, NROWS_F); k_pass2<0><<<g, 256>>>(nullptr, nullptr); }

    // pointwise contraction over c (Hermitian unpack fused into loads)
    k_einsum<<<(KEEP + KT - 1) / KT, 256>>>();

    // inverse: pass1 with fused inverse-pack, pass2 with fused depack+bias
    { dim3 g(16, NROWS_O); k_pass1<0><<<g, 256>>>(nullptr, nullptr); }
    { dim3 g(16, NROWS_O); k_pass2<1><<<g, 256>>>(out, bias); }
}

// round 8
// speedup vs baseline: 3.0970x; 1.0263x over previous
#include <cuda_runtime.h>
#include <cuda_fp16.h>

// ============================================================================
// Conv1Dfft via packed-real four-step FFT (M = 65536 = 256 x 256),
// register 16x16 FFT, fp16 global + fp16 smem intermediates, f32x2 math,
// register-tiled einsum.
// ============================================================================

#define M_FFT   65536
#define KEEP    32769          // bins 0..32768 kept (== M/2+1)
#define NROWS_X 256            // 32 n * 8 c
#define NROWS_W 128            // 16 f * 8 c
#define NROWS_F 384
#define NROWS_O 512            // 32 n * 16 f
#define OUT_W   65409

// ---------------- scratch (device globals; allocation-free) ----------------
__device__ __half2 g_A[(size_t)NROWS_F * M_FFT];   // fwd pass2 out (spectra Z)
__device__ __half2 g_B[(size_t)NROWS_O * M_FFT];   // pass1 out (both directions)
__device__ __half2 g_So[(size_t)NROWS_O * KEEP];   // product spectra
__device__ float2 g_twM[M_FFT];                    // e^{-2pi i j / 65536}
__device__ float2 g_tw2M[M_FFT];                   // e^{-2pi i j / 131072}

// ---------------- packed f32x2 complex helpers -----------------------------
static __device__ __forceinline__ float2 padd(float2 a, float2 b) {
    unsigned long long ua, ub, ur;
    asm("mov.b64 %0, {%1,%2};" : "=l"(ua) : "f"(a.x), "f"(a.y));
    asm("mov.b64 %0, {%1,%2};" : "=l"(ub) : "f"(b.x), "f"(b.y));
    asm("add.rn.f32x2 %0, %1, %2;" : "=l"(ur) : "l"(ua), "l"(ub));
    float2 o;
    asm("mov.b64 {%0,%1}, %2;" : "=f"(o.x), "=f"(o.y) : "l"(ur));
    return o;
}
static __device__ __forceinline__ float2 psub(float2 a, float2 b) {
    unsigned long long ua, ub, ur;
    const unsigned long long NEG1 = 0xBF800000BF800000ULL;  // (-1.f, -1.f)
    asm("mov.b64 %0, {%1,%2};" : "=l"(ua) : "f"(a.x), "f"(a.y));
    asm("mov.b64 %0, {%1,%2};" : "=l"(ub) : "f"(b.x), "f"(b.y));
    asm("fma.rn.f32x2 %0, %1, %2, %3;" : "=l"(ur) : "l"(ub), "l"(NEG1), "l"(ua));
    float2 o;
    asm("mov.b64 {%0,%1}, %2;" : "=f"(o.x), "=f"(o.y) : "l"(ur));
    return o;
}
static __device__ __forceinline__ float2 cmul(float2 a, float2 b) {
    return make_float2(fmaf(a.x, b.x, -(a.y * b.y)),
                       fmaf(a.x, b.y,   a.y * b.x));
}
static __device__ __forceinline__ float2 ldc(const __half2* p) {
    return __half22float2(*p);
}
static __device__ __forceinline__ void stc(__half2* p, float2 v) {
    *p = __float22half2_rn(v);
}

// ---------------- twiddle tables (fp32 sincospif, exact args) --------------
__global__ void k_init_tw() {
    int i = blockIdx.x * blockDim.x + threadIdx.x;
    if (i < M_FFT) {
        float s, c;
        sincospif(-(float)i / 32768.0f, &s, &c);
        g_twM[i] = make_float2(c, s);
        sincospif(-(float)i / 65536.0f, &s, &c);
        g_tw2M[i] = make_float2(c, s);
    }
}

// ---------------- 4-pt DFT on packed complex -------------------------------
static __device__ __forceinline__ void dft4(float2 x0, float2 x1, float2 x2,
                                            float2 x3, float2& y0, float2& y1,
                                            float2& y2, float2& y3) {
    float2 s0 = padd(x0, x2);
    float2 d0 = psub(x0, x2);
    float2 s1 = padd(x1, x3);
    float2 d1 = psub(x1, x3);
    y0 = padd(s0, s1);
    y2 = psub(s0, s1);
    float2 sw = make_float2(d1.y, -d1.x);   // -i*d1
    y1 = padd(d0, sw);
    y3 = psub(d0, sw);
}

// ---------------- 16-pt DFT in registers (radix-4 x radix-4) ---------------
__device__ __forceinline__ void fft16(float2 r[16]) {
    const float C1 = 0.9238795325112867f;
    const float S1 = 0.3826834323650898f;
    const float R2 = 0.7071067811865476f;
    float2 t[16];
    {
        float2 y0, y1, y2, y3;
        dft4(r[0], r[4], r[8], r[12], y0, y1, y2, y3);
        t[0] = y0; t[4] = y1; t[8] = y2; t[12] = y3;
    }
    {
        float2 y0, y1, y2, y3;
        dft4(r[1], r[5], r[9], r[13], y0, y1, y2, y3);
        t[1]  = y0;
        t[5]  = cmul(y1, make_float2( C1, -S1));
        t[9]  = cmul(y2, make_float2( R2, -R2));
        t[13] = cmul(y3, make_float2( S1, -C1));
    }
    {
        float2 y0, y1, y2, y3;
        dft4(r[2], r[6], r[10], r[14], y0, y1, y2, y3);
        t[2]  = y0;
        t[6]  = cmul(y1, make_float2( R2, -R2));
        t[10] = make_float2( y2.y, -y2.x);
        t[14] = cmul(y3, make_float2(-R2, -R2));
    }
    {
        float2 y0, y1, y2, y3;
        dft4(r[3], r[7], r[11], r[15], y0, y1, y2, y3);
        t[3]  = y0;
        t[7]  = cmul(y1, make_float2( S1, -C1));
        t[11] = cmul(y2, make_float2(-R2, -R2));
        t[15] = cmul(y3, make_float2(-C1,  S1));
    }
    #pragma unroll
    for (int p1 = 0; p1 < 4; p1++) {
        float2 y0, y1, y2, y3;
        dft4(t[4 * p1], t[4 * p1 + 1], t[4 * p1 + 2], t[4 * p1 + 3],
             y0, y1, y2, y3);
        r[p1] = y0; r[4 + p1] = y1; r[8 + p1] = y2; r[12 + p1] = y3;
    }
}

// pad-17 smem slot for pass-kernel tiles
#define SMI(u, c) ((u) * 17 + (c))

// ---------------- pass 1: 256-pt FFT over t1 + inter twiddle ---------------
// FWD=1: rows [0,256) from x, rows [256,384) from w.  FWD=0: inverse from g_So.
template <int FWD>
__global__ __launch_bounds__(256) void k_pass1(const float2* __restrict__ x,
                                               const float2* __restrict__ w) {
    __shared__ __half2 sm[4352];
    __shared__ float2 tw256[256];
    int tid = threadIdx.x;
    int c = tid & 15, s = tid >> 4;
    int t2 = blockIdx.x * 16 + c;
    int row = blockIdx.y;
    tw256[tid] = g_twM[tid << 8];

    float2 r[16];
    if (FWD) {
        if (row < NROWS_X) {
            const float2* xr = x + (size_t)row * 32768;
            #pragma unroll
            for (int a = 0; a < 16; a++)
                r[a] = (a < 8) ? xr[(a * 16 + s) * 256 + t2]
                               : make_float2(0.f, 0.f);
        } else {
            #pragma unroll
            for (int a = 0; a < 16; a++) r[a] = make_float2(0.f, 0.f);
            if (s == 0 && t2 < 64)
                r[0] = w[(size_t)(row - NROWS_X) * 64 + t2];
        }
    } else {  // inverse: packed-inverse input from g_So (conj trick, /M)
        const __half2* sr = g_So + (size_t)row * KEEP;
        const float inv = 1.0f / 65536.0f;
        #pragma unroll
        for (int a = 0; a < 16; a++) {
            int k = (a * 16 + s) * 256 + t2;
            float2 Sk = (k <= 32768) ? ldc(sr + k) : make_float2(0.f, 0.f);
            float2 Sm = (k >= 32768) ? ldc(sr + (M_FFT - k))
                                     : make_float2(0.f, 0.f);
            float2 E = make_float2(0.5f * (Sk.x + Sm.x), 0.5f * (Sk.y - Sm.y));
            float2 D = make_float2(Sk.x - Sm.x, Sk.y + Sm.y);
            float2 T = g_tw2M[k];
            float2 O = cmul(make_float2(T.x, -T.y), D);
            r[a] = make_float2((E.x - 0.5f * O.y) * inv,
                               -(E.y + 0.5f * O.x) * inv);
        }
    }
    __syncthreads();

    fft16(r);
    #pragma unroll
    for (int p = 0; p < 16; p++)
        stc(&sm[SMI(p * 16 + s, c)], cmul(r[p], tw256[s * p]));
    __syncthreads();
    #pragma unroll
    for (int b = 0; b < 16; b++)
        r[b] = ldc(&sm[SMI(s * 16 + b, c)]);
    fft16(r);                                // r[q] = X[16q + s]  (k1)

    float2 cur = g_twM[(s * t2) & (M_FFT - 1)];
    float2 stp = g_twM[(t2 << 4) & (M_FFT - 1)];
    __half2* dst = g_B + (size_t)row * M_FFT;
    #pragma unroll
    for (int q = 0; q < 16; q++) {
        int k1 = q * 16 + s;
        stc(dst + k1 * 256 + t2, cmul(r[q], cur));
        cur = cmul(cur, stp);
    }
}

// ---------------- pass 2: 256-pt FFT over t2, natural-order output ---------
template <int FINAL>
__global__ __launch_bounds__(256) void k_pass2(float* __restrict__ out,
                                               const float* __restrict__ bias) {
    __shared__ __half2 sm[4352];
    __shared__ float2 tw256[256];
    int tid = threadIdx.x;
    int c = tid & 15, s = tid >> 4;
    int row = blockIdx.y;
    int k1b = blockIdx.x * 16;
    tw256[tid] = g_twM[tid << 8];

    // coalesced staging: raw half2 copy (no conversion, no extra rounding)
    const __half2* src = g_B + (size_t)row * M_FFT + (size_t)k1b * 256;
    #pragma unroll
    for (int it = 0; it < 16; it++)
        sm[SMI(tid, it)] = src[it * 256 + tid];
    __syncthreads();

    float2 r[16];
    #pragma unroll
    for (int a = 0; a < 16; a++)
        r[a] = ldc(&sm[SMI(a * 16 + s, c)]);
    fft16(r);
    __syncthreads();
    #pragma unroll
    for (int p = 0; p < 16; p++)
        stc(&sm[SMI(p * 16 + s, c)], cmul(r[p], tw256[s * p]));
    __syncthreads();
    #pragma unroll
    for (int b = 0; b < 16; b++)
        r[b] = ldc(&sm[SMI(s * 16 + b, c)]);
    fft16(r);                                // r[q] = X[16q + s]  (k2)

    if (!FINAL) {
        __half2* dst = g_A + (size_t)row * M_FFT;
        #pragma unroll
        for (int q = 0; q < 16; q++)
            stc(dst + (q * 16 + s) * 256 + k1b + c, r[q]);
    } else {
        float bv = bias[row & 15];
        float* orow = out + (size_t)row * OUT_W;
        #pragma unroll
        for (int q = 0; q < 16; q++) {
            int m = (q * 16 + s) * 256 + k1b + c;   // packed time index
            int t = 2 * m;
            // scalar stores: row base is only 4B-aligned (OUT_W odd)
            if (t < OUT_W)     orow[t]     =  r[q].x + bv;
            if (t + 1 < OUT_W) orow[t + 1] = -r[q].y + bv;
        }
    }
}

// ---------------- einsum over c: 4n x 4f register tile, packed FMA ---------
// So[n,f,k] = sum_c X[n,c,k] * conj(Xw[f,c,k]);  X from Hermitian unpack.
#define KT 8
__global__ __launch_bounds__(256) void k_einsum() {
    __shared__ float2 XsF[NROWS_X * KT + 32];    // skewed: slot=8r+kk+(r>>3)
    __shared__ float2 Ws[NROWS_W][KT];
    int k0 = blockIdx.x * KT;
    int tid = threadIdx.x;

    // load + Hermitian unpack (packed math)
    for (int idx = tid; idx < NROWS_F * KT; idx += 256) {
        int r = idx >> 3, kq = idx & 7;
        int kg2 = k0 + kq;
        float2 X = make_float2(0.f, 0.f);
        if (kg2 < KEEP) {
            const __half2* zr = g_A + (size_t)r * M_FFT;
            float2 zk = ldc(zr + kg2);
            float2 zm = ldc(zr + ((M_FFT - kg2) & (M_FFT - 1)));
            float2 zmc = make_float2(zm.x, -zm.y);       // conj(zm)
            float2 E2 = padd(zk, zmc);                   // 2E
            float2 D  = psub(zk, zmc);
            float2 TD = cmul(g_tw2M[kg2], D);
            float2 S  = padd(E2, make_float2(TD.y, -TD.x));
            X = make_float2(0.5f * S.x, 0.5f * S.y);
        }
        if (r < NROWS_X) XsF[r * 8 + kq + (r >> 3)] = X;
        else             Ws[r - NROWS_X][kq] = X;
    }
    __syncthreads();

    int kk = tid & 7;
    int nb = ((tid >> 3) & 7) * 4;    // n base (0..28)
    int fb = (tid >> 6) * 4;          // f base (0..12)
    int kg = k0 + kk;

    unsigned long long acc[4][4];
    #pragma unroll
    for (int j = 0; j < 4; j++)
        #pragma unroll
        for (int i = 0; i < 4; i++) acc[j][i] = 0ULL;

    #pragma unroll
    for (int cc = 0; cc < 8; cc++) {
        // pack 4 W values: pb1=(b.x,-b.y), pb2=(b.y,b.x)
        unsigned long long pb1[4], pb2[4];
        #pragma unroll
        for (int i = 0; i < 4; i++) {
            float2 b = Ws[(fb + i) * 8 + cc][kk];
            float nby = -b.y;
            asm("mov.b64 %0, {%1,%2};" : "=l"(pb1[i]) : "f"(b.x), "f"(nby));
            asm("mov.b64 %0, {%1,%2};" : "=l"(pb2[i]) : "f"(b.y), "f"(b.x));
        }
        #pragma unroll
        for (int j = 0; j < 4; j++) {
            int rr = (nb + j) * 8 + cc;
            float2 a = XsF[rr * 8 + kk + (rr >> 3)];
            unsigned long long sax, say;
            asm("mov.b64 %0, {%1,%1};" : "=l"(sax) : "f"(a.x));
            asm("mov.b64 %0, {%1,%1};" : "=l"(say) : "f"(a.y));
            #pragma unroll
            for (int i = 0; i < 4; i++) {
                // acc = (out.x, out.y); out += a * conj(b)
                asm("fma.rn.f32x2 %0, %1, %2, %0;" : "+l"(acc[j][i])
                    : "l"(pb1[i]), "l"(sax));
                asm("fma.rn.f32x2 %0, %1, %2, %0;" : "+l"(acc[j][i])
                    : "l"(pb2[i]), "l"(say));
            }
        }
    }

    if (kg < KEEP) {
        #pragma unroll
        for (int j = 0; j < 4; j++)
            #pragma unroll
            for (int i = 0; i < 4; i++) {
                float2 o;
                asm("mov.b64 {%0,%1}, %2;" : "=f"(o.x), "=f"(o.y)
                    : "l"(acc[j][i]));
                stc(g_So + (size_t)((nb + j) * 16 + fb + i) * KEEP + kg, o);
            }
    }
}

// ============================================================================
extern "C" void kernel_launch(void* const* d_in, const int* in_sizes, int n_in,
                              void* d_out, int out_size) {
    const float2* x    = (const float2*)d_in[0];
    const float2* w    = (const float2*)d_in[1];
    const float*  bias = (const float*)d_in[2];
    float* out = (float*)d_out;

    k_init_tw<<<(M_FFT + 255) / 256, 256>>>();

    // forward: pass1 (x rows + w rows in one launch), pass2
    { dim3 g(16, NROWS_F); k_pass1<1><<<g, 256>>>(x, w); }
    { dim3 g(16, NROWS_F); k_pass2<0><<<g, 256>>>(nullptr, nullptr); }

    // pointwise contraction over c (Hermitian unpack fused into loads)
    k_einsum<<<(KEEP + KT - 1) / KT, 256>>>();

    // inverse: pass1 with fused inverse-pack, pass2 with fused depack+bias
    { dim3 g(16, NROWS_O); k_pass1<0><<<g, 256>>>(nullptr, nullptr); }
    { dim3 g(16, NROWS_O); k_pass2<1><<<g, 256>>>(out, bias); }
}

// round 9
// speedup vs baseline: 3.3332x; 1.0763x over previous
#include <cuda_runtime.h>
#include <cuda_fp16.h>

// ============================================================================
// Conv1Dfft via packed-real four-step FFT (M = 65536 = 256 x 256),
// register 16x16 FFT, fp16 global + fp16 smem intermediates, f32x2 math,
// register-tiled einsum with prefetched loads.
// ============================================================================

#define M_FFT   65536
#define KEEP    32769          // bins 0..32768 kept (== M/2+1)
#define NROWS_X 256            // 32 n * 8 c
#define NROWS_W 128            // 16 f * 8 c
#define NROWS_F 384
#define NROWS_O 512            // 32 n * 16 f
#define OUT_W   65409

// ---------------- scratch (device globals; allocation-free) ----------------
__device__ __half2 g_A[(size_t)NROWS_F * M_FFT];   // fwd pass2 out (spectra Z)
__device__ __half2 g_B[(size_t)NROWS_O * M_FFT];   // pass1 out (both directions)
__device__ __half2 g_So[(size_t)NROWS_O * KEEP];   // product spectra
__device__ float2 g_twM[M_FFT];                    // e^{-2pi i j / 65536}
__device__ float2 g_tw2M[M_FFT];                   // e^{-2pi i j / 131072}

// ---------------- packed f32x2 complex helpers -----------------------------
static __device__ __forceinline__ float2 padd(float2 a, float2 b) {
    unsigned long long ua, ub, ur;
    asm("mov.b64 %0, {%1,%2};" : "=l"(ua) : "f"(a.x), "f"(a.y));
    asm("mov.b64 %0, {%1,%2};" : "=l"(ub) : "f"(b.x), "f"(b.y));
    asm("add.rn.f32x2 %0, %1, %2;" : "=l"(ur) : "l"(ua), "l"(ub));
    float2 o;
    asm("mov.b64 {%0,%1}, %2;" : "=f"(o.x), "=f"(o.y) : "l"(ur));
    return o;
}
static __device__ __forceinline__ float2 psub(float2 a, float2 b) {
    unsigned long long ua, ub, ur;
    const unsigned long long NEG1 = 0xBF800000BF800000ULL;  // (-1.f, -1.f)
    asm("mov.b64 %0, {%1,%2};" : "=l"(ua) : "f"(a.x), "f"(a.y));
    asm("mov.b64 %0, {%1,%2};" : "=l"(ub) : "f"(b.x), "f"(b.y));
    asm("fma.rn.f32x2 %0, %1, %2, %3;" : "=l"(ur) : "l"(ub), "l"(NEG1), "l"(ua));
    float2 o;
    asm("mov.b64 {%0,%1}, %2;" : "=f"(o.x), "=f"(o.y) : "l"(ur));
    return o;
}
static __device__ __forceinline__ float2 cmul(float2 a, float2 b) {
    return make_float2(fmaf(a.x, b.x, -(a.y * b.y)),
                       fmaf(a.x, b.y,   a.y * b.x));
}
static __device__ __forceinline__ float2 ldc(const __half2* p) {
    return __half22float2(*p);
}
static __device__ __forceinline__ void stc(__half2* p, float2 v) {
    *p = __float22half2_rn(v);
}

// ---------------- twiddle tables (fp32 sincospif, exact args) --------------
__global__ void k_init_tw() {
    int i = blockIdx.x * blockDim.x + threadIdx.x;
    if (i < M_FFT) {
        float s, c;
        sincospif(-(float)i / 32768.0f, &s, &c);
        g_twM[i] = make_float2(c, s);
        sincospif(-(float)i / 65536.0f, &s, &c);
        g_tw2M[i] = make_float2(c, s);
    }
}

// ---------------- 4-pt DFT on packed complex -------------------------------
static __device__ __forceinline__ void dft4(float2 x0, float2 x1, float2 x2,
                                            float2 x3, float2& y0, float2& y1,
                                            float2& y2, float2& y3) {
    float2 s0 = padd(x0, x2);
    float2 d0 = psub(x0, x2);
    float2 s1 = padd(x1, x3);
    float2 d1 = psub(x1, x3);
    y0 = padd(s0, s1);
    y2 = psub(s0, s1);
    float2 sw = make_float2(d1.y, -d1.x);   // -i*d1
    y1 = padd(d0, sw);
    y3 = psub(d0, sw);
}

// ---------------- 16-pt DFT in registers (radix-4 x radix-4) ---------------
__device__ __forceinline__ void fft16(float2 r[16]) {
    const float C1 = 0.9238795325112867f;
    const float S1 = 0.3826834323650898f;
    const float R2 = 0.7071067811865476f;
    float2 t[16];
    {
        float2 y0, y1, y2, y3;
        dft4(r[0], r[4], r[8], r[12], y0, y1, y2, y3);
        t[0] = y0; t[4] = y1; t[8] = y2; t[12] = y3;
    }
    {
        float2 y0, y1, y2, y3;
        dft4(r[1], r[5], r[9], r[13], y0, y1, y2, y3);
        t[1]  = y0;
        t[5]  = cmul(y1, make_float2( C1, -S1));
        t[9]  = cmul(y2, make_float2( R2, -R2));
        t[13] = cmul(y3, make_float2( S1, -C1));
    }
    {
        float2 y0, y1, y2, y3;
        dft4(r[2], r[6], r[10], r[14], y0, y1, y2, y3);
        t[2]  = y0;
        t[6]  = cmul(y1, make_float2( R2, -R2));
        t[10] = make_float2( y2.y, -y2.x);
        t[14] = cmul(y3, make_float2(-R2, -R2));
    }
    {
        float2 y0, y1, y2, y3;
        dft4(r[3], r[7], r[11], r[15], y0, y1, y2, y3);
        t[3]  = y0;
        t[7]  = cmul(y1, make_float2( S1, -C1));
        t[11] = cmul(y2, make_float2(-R2, -R2));
        t[15] = cmul(y3, make_float2(-C1,  S1));
    }
    #pragma unroll
    for (int p1 = 0; p1 < 4; p1++) {
        float2 y0, y1, y2, y3;
        dft4(t[4 * p1], t[4 * p1 + 1], t[4 * p1 + 2], t[4 * p1 + 3],
             y0, y1, y2, y3);
        r[p1] = y0; r[4 + p1] = y1; r[8 + p1] = y2; r[12 + p1] = y3;
    }
}

// pad-17 smem slot for pass-kernel tiles
#define SMI(u, c) ((u) * 17 + (c))

// ---------------- pass 1: 256-pt FFT over t1 + inter twiddle ---------------
// FWD=1: rows [0,256) from x, rows [256,384) from w.  FWD=0: inverse from g_So.
template <int FWD>
__global__ __launch_bounds__(256) void k_pass1(const float2* __restrict__ x,
                                               const float2* __restrict__ w) {
    __shared__ __half2 sm[4352];
    __shared__ float2 tw256[256];
    int tid = threadIdx.x;
    int c = tid & 15, s = tid >> 4;
    int t2 = blockIdx.x * 16 + c;
    int row = blockIdx.y;
    tw256[tid] = g_twM[tid << 8];

    float2 r[16];
    if (FWD) {
        if (row < NROWS_X) {
            const float2* xr = x + (size_t)row * 32768;
            #pragma unroll
            for (int a = 0; a < 16; a++)
                r[a] = (a < 8) ? xr[(a * 16 + s) * 256 + t2]
                               : make_float2(0.f, 0.f);
        } else {
            #pragma unroll
            for (int a = 0; a < 16; a++) r[a] = make_float2(0.f, 0.f);
            if (s == 0 && t2 < 64)
                r[0] = w[(size_t)(row - NROWS_X) * 64 + t2];
        }
    } else {  // inverse: packed-inverse input from g_So (conj trick, /M)
        const __half2* sr = g_So + (size_t)row * KEEP;
        const float inv = 1.0f / 65536.0f;
        #pragma unroll
        for (int a = 0; a < 16; a++) {
            int k = (a * 16 + s) * 256 + t2;
            float2 Sk = (k <= 32768) ? ldc(sr + k) : make_float2(0.f, 0.f);
            float2 Sm = (k >= 32768) ? ldc(sr + (M_FFT - k))
                                     : make_float2(0.f, 0.f);
            float2 E = make_float2(0.5f * (Sk.x + Sm.x), 0.5f * (Sk.y - Sm.y));
            float2 D = make_float2(Sk.x - Sm.x, Sk.y + Sm.y);
            float2 T = g_tw2M[k];
            float2 O = cmul(make_float2(T.x, -T.y), D);
            r[a] = make_float2((E.x - 0.5f * O.y) * inv,
                               -(E.y + 0.5f * O.x) * inv);
        }
    }
    __syncthreads();

    fft16(r);
    #pragma unroll
    for (int p = 0; p < 16; p++)
        stc(&sm[SMI(p * 16 + s, c)], cmul(r[p], tw256[s * p]));
    __syncthreads();
    #pragma unroll
    for (int b = 0; b < 16; b++)
        r[b] = ldc(&sm[SMI(s * 16 + b, c)]);
    fft16(r);                                // r[q] = X[16q + s]  (k1)

    float2 cur = g_twM[(s * t2) & (M_FFT - 1)];
    float2 stp = g_twM[(t2 << 4) & (M_FFT - 1)];
    __half2* dst = g_B + (size_t)row * M_FFT;
    #pragma unroll
    for (int q = 0; q < 16; q++) {
        int k1 = q * 16 + s;
        stc(dst + k1 * 256 + t2, cmul(r[q], cur));
        cur = cmul(cur, stp);
    }
}

// ---------------- pass 2: 256-pt FFT over t2, natural-order output ---------
template <int FINAL>
__global__ __launch_bounds__(256) void k_pass2(float* __restrict__ out,
                                               const float* __restrict__ bias) {
    __shared__ __half2 sm[4352];
    __shared__ float2 tw256[256];
    int tid = threadIdx.x;
    int c = tid & 15, s = tid >> 4;
    int row = blockIdx.y;
    int k1b = blockIdx.x * 16;
    tw256[tid] = g_twM[tid << 8];

    // coalesced staging: raw half2 copy (no conversion, no extra rounding)
    const __half2* src = g_B + (size_t)row * M_FFT + (size_t)k1b * 256;
    #pragma unroll
    for (int it = 0; it < 16; it++)
        sm[SMI(tid, it)] = src[it * 256 + tid];
    __syncthreads();

    float2 r[16];
    #pragma unroll
    for (int a = 0; a < 16; a++)
        r[a] = ldc(&sm[SMI(a * 16 + s, c)]);
    fft16(r);
    __syncthreads();
    #pragma unroll
    for (int p = 0; p < 16; p++)
        stc(&sm[SMI(p * 16 + s, c)], cmul(r[p], tw256[s * p]));
    __syncthreads();
    #pragma unroll
    for (int b = 0; b < 16; b++)
        r[b] = ldc(&sm[SMI(s * 16 + b, c)]);
    fft16(r);                                // r[q] = X[16q + s]  (k2)

    if (!FINAL) {
        __half2* dst = g_A + (size_t)row * M_FFT;
        #pragma unroll
        for (int q = 0; q < 16; q++)
            stc(dst + (q * 16 + s) * 256 + k1b + c, r[q]);
    } else {
        float bv = bias[row & 15];
        float* orow = out + (size_t)row * OUT_W;
        #pragma unroll
        for (int q = 0; q < 16; q++) {
            int m = (q * 16 + s) * 256 + k1b + c;   // packed time index
            int t = 2 * m;
            // scalar stores: row base is only 4B-aligned (OUT_W odd)
            if (t < OUT_W)     orow[t]     =  r[q].x + bv;
            if (t + 1 < OUT_W) orow[t + 1] = -r[q].y + bv;
        }
    }
}

// ---------------- einsum over c: 4n x 4f register tile, packed FMA ---------
// KT=16 bins/block; prefetched global loads; two sequential k-passes.
#define KT 16
__global__ __launch_bounds__(256) void k_einsum() {
    __shared__ float2 XsF[NROWS_X * KT + 64];    // skewed: slot=16r+kq+(r>>3)
    __shared__ float2 Ws[NROWS_W][KT];
    int k0 = blockIdx.x * KT;
    int tid = threadIdx.x;

    // load + Hermitian unpack: prefetch batches of 12 (zk, zm) pairs
    #pragma unroll
    for (int hb = 0; hb < 2; hb++) {
        __half2 bk[12], bm[12];
        #pragma unroll
        for (int ii = 0; ii < 12; ii++) {
            int idx = (hb * 12 + ii) * 256 + tid;
            int r = idx >> 4, kq = idx & 15;
            int kg2 = k0 + kq;
            const __half2* zr = g_A + (size_t)r * M_FFT;
            bool ok = (kg2 < KEEP);
            bk[ii] = ok ? zr[kg2] : __float2half2_rn(0.f);
            bm[ii] = ok ? zr[(M_FFT - kg2) & (M_FFT - 1)]
                        : __float2half2_rn(0.f);
        }
        #pragma unroll
        for (int ii = 0; ii < 12; ii++) {
            int idx = (hb * 12 + ii) * 256 + tid;
            int r = idx >> 4, kq = idx & 15;
            int kg2 = k0 + kq;
            float2 zk = __half22float2(bk[ii]);
            float2 zm = __half22float2(bm[ii]);
            float2 zmc = make_float2(zm.x, -zm.y);       // conj(zm)
            float2 E2 = padd(zk, zmc);                   // 2E
            float2 D  = psub(zk, zmc);
            float2 TD = cmul(g_tw2M[kg2], D);
            float2 S  = padd(E2, make_float2(TD.y, -TD.x));
            float2 X  = make_float2(0.5f * S.x, 0.5f * S.y);
            if (r < NROWS_X) XsF[r * 16 + kq + (r >> 3)] = X;
            else             Ws[r - NROWS_X][kq] = X;
        }
    }
    __syncthreads();

    int kk = tid & 7;
    int nb = ((tid >> 3) & 7) * 4;    // n base (0..28)
    int fb = (tid >> 6) * 4;          // f base (0..12)

    #pragma unroll
    for (int p = 0; p < 2; p++) {
        int kq = kk + 8 * p;
        int kg = k0 + kq;

        unsigned long long acc[4][4];
        #pragma unroll
        for (int j = 0; j < 4; j++)
            #pragma unroll
            for (int i = 0; i < 4; i++) acc[j][i] = 0ULL;

        #pragma unroll
        for (int cc = 0; cc < 8; cc++) {
            // pack 4 W values: pb1=(b.x,-b.y), pb2=(b.y,b.x)
            unsigned long long pb1[4], pb2[4];
            #pragma unroll
            for (int i = 0; i < 4; i++) {
                float2 b = Ws[(fb + i) * 8 + cc][kq];
                float nby = -b.y;
                asm("mov.b64 %0, {%1,%2};" : "=l"(pb1[i]) : "f"(b.x), "f"(nby));
                asm("mov.b64 %0, {%1,%2};" : "=l"(pb2[i]) : "f"(b.y), "f"(b.x));
            }
            #pragma unroll
            for (int j = 0; j < 4; j++) {
                int rr = (nb + j) * 8 + cc;
                float2 a = XsF[rr * 16 + kq + (rr >> 3)];
                unsigned long long sax, say;
                asm("mov.b64 %0, {%1,%1};" : "=l"(sax) : "f"(a.x));
                asm("mov.b64 %0, {%1,%1};" : "=l"(say) : "f"(a.y));
                #pragma unroll
                for (int i = 0; i < 4; i++) {
                    // acc = (out.x, out.y); out += a * conj(b)
                    asm("fma.rn.f32x2 %0, %1, %2, %0;" : "+l"(acc[j][i])
                        : "l"(pb1[i]), "l"(sax));
                    asm("fma.rn.f32x2 %0, %1, %2, %0;" : "+l"(acc[j][i])
                        : "l"(pb2[i]), "l"(say));
                }
            }
        }

        if (kg < KEEP) {
            #pragma unroll
            for (int j = 0; j < 4; j++)
                #pragma unroll
                for (int i = 0; i < 4; i++) {
                    float2 o;
                    asm("mov.b64 {%0,%1}, %2;" : "=f"(o.x), "=f"(o.y)
                        : "l"(acc[j][i]));
                    stc(g_So + (size_t)((nb + j) * 16 + fb + i) * KEEP + kg, o);
                }
        }
    }
}

// ============================================================================
extern "C" void kernel_launch(void* const* d_in, const int* in_sizes, int n_in,
                              void* d_out, int out_size) {
    const float2* x    = (const float2*)d_in[0];
    const float2* w    = (const float2*)d_in[1];
    const float*  bias = (const float*)d_in[2];
    float* out = (float*)d_out;

    k_init_tw<<<(M_FFT + 255) / 256, 256>>>();

    // forward: pass1 (x rows + w rows in one launch), pass2
    { dim3 g(16, NROWS_F); k_pass1<1><<<g, 256>>>(x, w); }
    { dim3 g(16, NROWS_F); k_pass2<0><<<g, 256>>>(nullptr, nullptr); }

    // pointwise contraction over c (Hermitian unpack fused into loads)
    k_einsum<<<(KEEP + KT - 1) / KT, 256>>>();

    // inverse: pass1 with fused inverse-pack, pass2 with fused depack+bias
    { dim3 g(16, NROWS_O); k_pass1<0><<<g, 256>>>(nullptr, nullptr); }
    { dim3 g(16, NROWS_O); k_pass2<1><<<g, 256>>>(out, bias); }
}

// round 10
// speedup vs baseline: 4.2588x; 1.2777x over previous
#include <cuda_runtime.h>
#include <cuda_fp16.h>

// ============================================================================
// Conv1Dfft via packed-real four-step FFT (M = 65536 = 256 x 256),
// register 16x16 FFT, fp16 global + fp16 smem intermediates, f32x2 math,
// register-tiled einsum, specialized inverse unpack.
// ============================================================================

#define M_FFT   65536
#define KEEP    32769          // bins 0..32768 kept (== M/2+1)
#define NROWS_X 256            // 32 n * 8 c
#define NROWS_W 128            // 16 f * 8 c
#define NROWS_F 384
#define NROWS_O 512            // 32 n * 16 f
#define OUT_W   65409

// ---------------- scratch (device globals; allocation-free) ----------------
__device__ __half2 g_A[(size_t)NROWS_F * M_FFT];   // fwd pass2 out (spectra Z)
__device__ __half2 g_B[(size_t)NROWS_O * M_FFT];   // pass1 out (both directions)
__device__ __half2 g_So[(size_t)NROWS_O * KEEP];   // product spectra
__device__ float2 g_twM[M_FFT];                    // e^{-2pi i j / 65536}
__device__ float2 g_tw2M[M_FFT];                   // e^{-2pi i j / 131072}

// ---------------- packed f32x2 complex helpers -----------------------------
static __device__ __forceinline__ float2 padd(float2 a, float2 b) {
    unsigned long long ua, ub, ur;
    asm("mov.b64 %0, {%1,%2};" : "=l"(ua) : "f"(a.x), "f"(a.y));
    asm("mov.b64 %0, {%1,%2};" : "=l"(ub) : "f"(b.x), "f"(b.y));
    asm("add.rn.f32x2 %0, %1, %2;" : "=l"(ur) : "l"(ua), "l"(ub));
    float2 o;
    asm("mov.b64 {%0,%1}, %2;" : "=f"(o.x), "=f"(o.y) : "l"(ur));
    return o;
}
static __device__ __forceinline__ float2 psub(float2 a, float2 b) {
    unsigned long long ua, ub, ur;
    const unsigned long long NEG1 = 0xBF800000BF800000ULL;  // (-1.f, -1.f)
    asm("mov.b64 %0, {%1,%2};" : "=l"(ua) : "f"(a.x), "f"(a.y));
    asm("mov.b64 %0, {%1,%2};" : "=l"(ub) : "f"(b.x), "f"(b.y));
    asm("fma.rn.f32x2 %0, %1, %2, %3;" : "=l"(ur) : "l"(ub), "l"(NEG1), "l"(ua));
    float2 o;
    asm("mov.b64 {%0,%1}, %2;" : "=f"(o.x), "=f"(o.y) : "l"(ur));
    return o;
}
static __device__ __forceinline__ float2 cmul(float2 a, float2 b) {
    return make_float2(fmaf(a.x, b.x, -(a.y * b.y)),
                       fmaf(a.x, b.y,   a.y * b.x));
}
static __device__ __forceinline__ float2 ldc(const __half2* p) {
    return __half22float2(*p);
}
static __device__ __forceinline__ void stc(__half2* p, float2 v) {
    *p = __float22half2_rn(v);
}

// ---------------- twiddle tables (fp32 sincospif, exact args) --------------
__global__ void k_init_tw() {
    int i = blockIdx.x * blockDim.x + threadIdx.x;
    if (i < M_FFT) {
        float s, c;
        sincospif(-(float)i / 32768.0f, &s, &c);
        g_twM[i] = make_float2(c, s);
        sincospif(-(float)i / 65536.0f, &s, &c);
        g_tw2M[i] = make_float2(c, s);
    }
}

// ---------------- 4-pt DFT on packed complex -------------------------------
static __device__ __forceinline__ void dft4(float2 x0, float2 x1, float2 x2,
                                            float2 x3, float2& y0, float2& y1,
                                            float2& y2, float2& y3) {
    float2 s0 = padd(x0, x2);
    float2 d0 = psub(x0, x2);
    float2 s1 = padd(x1, x3);
    float2 d1 = psub(x1, x3);
    y0 = padd(s0, s1);
    y2 = psub(s0, s1);
    float2 sw = make_float2(d1.y, -d1.x);   // -i*d1
    y1 = padd(d0, sw);
    y3 = psub(d0, sw);
}

// ---------------- 16-pt DFT in registers (radix-4 x radix-4) ---------------
__device__ __forceinline__ void fft16(float2 r[16]) {
    const float C1 = 0.9238795325112867f;
    const float S1 = 0.3826834323650898f;
    const float R2 = 0.7071067811865476f;
    float2 t[16];
    {
        float2 y0, y1, y2, y3;
        dft4(r[0], r[4], r[8], r[12], y0, y1, y2, y3);
        t[0] = y0; t[4] = y1; t[8] = y2; t[12] = y3;
    }
    {
        float2 y0, y1, y2, y3;
        dft4(r[1], r[5], r[9], r[13], y0, y1, y2, y3);
        t[1]  = y0;
        t[5]  = cmul(y1, make_float2( C1, -S1));
        t[9]  = cmul(y2, make_float2( R2, -R2));
        t[13] = cmul(y3, make_float2( S1, -C1));
    }
    {
        float2 y0, y1, y2, y3;
        dft4(r[2], r[6], r[10], r[14], y0, y1, y2, y3);
        t[2]  = y0;
        t[6]  = cmul(y1, make_float2( R2, -R2));
        t[10] = make_float2( y2.y, -y2.x);
        t[14] = cmul(y3, make_float2(-R2, -R2));
    }
    {
        float2 y0, y1, y2, y3;
        dft4(r[3], r[7], r[11], r[15], y0, y1, y2, y3);
        t[3]  = y0;
        t[7]  = cmul(y1, make_float2( S1, -C1));
        t[11] = cmul(y2, make_float2(-R2, -R2));
        t[15] = cmul(y3, make_float2(-C1,  S1));
    }
    #pragma unroll
    for (int p1 = 0; p1 < 4; p1++) {
        float2 y0, y1, y2, y3;
        dft4(t[4 * p1], t[4 * p1 + 1], t[4 * p1 + 2], t[4 * p1 + 3],
             y0, y1, y2, y3);
        r[p1] = y0; r[4 + p1] = y1; r[8 + p1] = y2; r[12 + p1] = y3;
    }
}

// pad-17 smem slot for pass-kernel tiles
#define SMI(u, c) ((u) * 17 + (c))

// ---------------- pass 1: 256-pt FFT over t1 + inter twiddle ---------------
// FWD=1: rows [0,256) from x, rows [256,384) from w.  FWD=0: inverse from g_So.
template <int FWD>
__global__ __launch_bounds__(256) void k_pass1(const float2* __restrict__ x,
                                               const float2* __restrict__ w) {
    __shared__ __half2 sm[4352];
    __shared__ float2 tw256[256];
    int tid = threadIdx.x;
    int c = tid & 15, s = tid >> 4;
    int t2 = blockIdx.x * 16 + c;
    int row = blockIdx.y;
    tw256[tid] = g_twM[tid << 8];

    float2 r[16];
    if (FWD) {
        if (row < NROWS_X) {
            const float2* xr = x + (size_t)row * 32768;
            #pragma unroll
            for (int a = 0; a < 16; a++)
                r[a] = (a < 8) ? xr[(a * 16 + s) * 256 + t2]
                               : make_float2(0.f, 0.f);
        } else {
            #pragma unroll
            for (int a = 0; a < 16; a++) r[a] = make_float2(0.f, 0.f);
            if (s == 0 && t2 < 64)
                r[0] = w[(size_t)(row - NROWS_X) * 64 + t2];
        }
    } else {
        // inverse packed input from g_So (conj trick, /M).
        // lower half (a<8): k < 32768 -> mirror bin (65536-k) > 32768 is zero.
        // upper half (a>=8): k >= 32768 -> direct bin is zero except k=32768,
        //   where the mirror formula is exact (verified algebraically).
        const __half2* sr = g_So + (size_t)row * KEEP;
        const float hinv = 0.5f / 65536.0f;
        float2 S[8];
        #pragma unroll
        for (int a = 0; a < 8; a++)
            S[a] = ldc(sr + (a * 16 + s) * 256 + t2);
        #pragma unroll
        for (int a = 0; a < 8; a++) {
            int k = (a * 16 + s) * 256 + t2;
            float2 T = g_tw2M[k];                 // Tc = (T.x, -T.y)
            // O = cmul(Tc, S)
            float Ox = fmaf(T.x, S[a].x,  T.y * S[a].y);
            float Oy = fmaf(T.x, S[a].y, -(T.y * S[a].x));
            r[a] = make_float2((S[a].x - Oy) * hinv, -(S[a].y + Ox) * hinv);
        }
        #pragma unroll
        for (int a = 8; a < 16; a++)
            S[a - 8] = ldc(sr + (M_FFT - ((a * 16 + s) * 256 + t2)));
        #pragma unroll
        for (int a = 8; a < 16; a++) {
            int k = (a * 16 + s) * 256 + t2;
            float2 Sm = S[a - 8];
            float2 T = g_tw2M[k];
            // O = cmul((T.x,-T.y), (-Sm.x, Sm.y))
            float Ox = fmaf(-T.x, Sm.x,  T.y * Sm.y);
            float Oy = fmaf( T.x, Sm.y,  T.y * Sm.x);
            r[a] = make_float2((Sm.x - Oy) * hinv, (Sm.y - Ox) * hinv);
        }
    }
    __syncthreads();

    fft16(r);
    #pragma unroll
    for (int p = 0; p < 16; p++)
        stc(&sm[SMI(p * 16 + s, c)], cmul(r[p], tw256[s * p]));
    __syncthreads();
    #pragma unroll
    for (int b = 0; b < 16; b++)
        r[b] = ldc(&sm[SMI(s * 16 + b, c)]);
    fft16(r);                                // r[q] = X[16q + s]  (k1)

    float2 cur = g_twM[(s * t2) & (M_FFT - 1)];
    float2 stp = g_twM[(t2 << 4) & (M_FFT - 1)];
    __half2* dst = g_B + (size_t)row * M_FFT;
    #pragma unroll
    for (int q = 0; q < 16; q++) {
        int k1 = q * 16 + s;
        stc(dst + k1 * 256 + t2, cmul(r[q], cur));
        cur = cmul(cur, stp);
    }
}

// ---------------- pass 2: 256-pt FFT over t2, natural-order output ---------
template <int FINAL>
__global__ __launch_bounds__(256) void k_pass2(float* __restrict__ out,
                                               const float* __restrict__ bias) {
    __shared__ __half2 sm[4352];
    __shared__ float2 tw256[256];
    int tid = threadIdx.x;
    int c = tid & 15, s = tid >> 4;
    int row = blockIdx.y;
    int k1b = blockIdx.x * 16;
    tw256[tid] = g_twM[tid << 8];

    // coalesced staging: raw half2 copy (no conversion, no extra rounding)
    const __half2* src = g_B + (size_t)row * M_FFT + (size_t)k1b * 256;
    #pragma unroll
    for (int it = 0; it < 16; it++)
        sm[SMI(tid, it)] = src[it * 256 + tid];
    __syncthreads();

    float2 r[16];
    #pragma unroll
    for (int a = 0; a < 16; a++)
        r[a] = ldc(&sm[SMI(a * 16 + s, c)]);
    fft16(r);
    __syncthreads();
    #pragma unroll
    for (int p = 0; p < 16; p++)
        stc(&sm[SMI(p * 16 + s, c)], cmul(r[p], tw256[s * p]));
    __syncthreads();
    #pragma unroll
    for (int b = 0; b < 16; b++)
        r[b] = ldc(&sm[SMI(s * 16 + b, c)]);
    fft16(r);                                // r[q] = X[16q + s]  (k2)

    if (!FINAL) {
        __half2* dst = g_A + (size_t)row * M_FFT;
        #pragma unroll
        for (int q = 0; q < 16; q++)
            stc(dst + (q * 16 + s) * 256 + k1b + c, r[q]);
    } else {
        float bv = bias[row & 15];
        float* orow = out + (size_t)row * OUT_W;
        #pragma unroll
        for (int q = 0; q < 16; q++) {
            int m = (q * 16 + s) * 256 + k1b + c;   // packed time index
            int t = 2 * m;
            // scalar stores: row base is only 4B-aligned (OUT_W odd)
            if (t < OUT_W)     orow[t]     =  r[q].x + bv;
            if (t + 1 < OUT_W) orow[t + 1] = -r[q].y + bv;
        }
    }
}

// ---------------- einsum over c: 4n x 4f register tile, packed FMA ---------
// KT=16 bins/block; prefetched global loads; two sequential k-passes.
#define KT 16
__global__ __launch_bounds__(256, 4) void k_einsum() {
    __shared__ float2 XsF[NROWS_X * KT + 64];    // skewed: slot=16r+kq+(r>>3)
    __shared__ float2 Ws[NROWS_W][KT];
    int k0 = blockIdx.x * KT;
    int tid = threadIdx.x;

    // load + Hermitian unpack: prefetch batches of 12 (zk, zm) pairs
    #pragma unroll
    for (int hb = 0; hb < 2; hb++) {
        __half2 bk[12], bm[12];
        #pragma unroll
        for (int ii = 0; ii < 12; ii++) {
            int idx = (hb * 12 + ii) * 256 + tid;
            int r = idx >> 4, kq = idx & 15;
            int kg2 = k0 + kq;
            const __half2* zr = g_A + (size_t)r * M_FFT;
            bool ok = (kg2 < KEEP);
            bk[ii] = ok ? zr[kg2] : __float2half2_rn(0.f);
            bm[ii] = ok ? zr[(M_FFT - kg2) & (M_FFT - 1)]
                        : __float2half2_rn(0.f);
        }
        #pragma unroll
        for (int ii = 0; ii < 12; ii++) {
            int idx = (hb * 12 + ii) * 256 + tid;
            int r = idx >> 4, kq = idx & 15;
            int kg2 = k0 + kq;
            float2 zk = __half22float2(bk[ii]);
            float2 zm = __half22float2(bm[ii]);
            float2 zmc = make_float2(zm.x, -zm.y);       // conj(zm)
            float2 E2 = padd(zk, zmc);                   // 2E
            float2 D  = psub(zk, zmc);
            float2 TD = cmul(g_tw2M[kg2], D);
            float2 S  = padd(E2, make_float2(TD.y, -TD.x));
            float2 X  = make_float2(0.5f * S.x, 0.5f * S.y);
            if (r < NROWS_X) XsF[r * 16 + kq + (r >> 3)] = X;
            else             Ws[r - NROWS_X][kq] = X;
        }
    }
    __syncthreads();

    int kk = tid & 7;
    int nb = ((tid >> 3) & 7) * 4;    // n base (0..28)
    int fb = (tid >> 6) * 4;          // f base (0..12)

    #pragma unroll
    for (int p = 0; p < 2; p++) {
        int kq = kk + 8 * p;
        int kg = k0 + kq;

        unsigned long long acc[4][4];
        #pragma unroll
        for (int j = 0; j < 4; j++)
            #pragma unroll
            for (int i = 0; i < 4; i++) acc[j][i] = 0ULL;

        #pragma unroll
        for (int cc = 0; cc < 8; cc++) {
            // pack 4 W values: pb1=(b.x,-b.y), pb2=(b.y,b.x)
            unsigned long long pb1[4], pb2[4];
            #pragma unroll
            for (int i = 0; i < 4; i++) {
                float2 b = Ws[(fb + i) * 8 + cc][kq];
                float nby = -b.y;
                asm("mov.b64 %0, {%1,%2};" : "=l"(pb1[i]) : "f"(b.x), "f"(nby));
                asm("mov.b64 %0, {%1,%2};" : "=l"(pb2[i]) : "f"(b.y), "f"(b.x));
            }
            #pragma unroll
            for (int j = 0; j < 4; j++) {
                int rr = (nb + j) * 8 + cc;
                float2 a = XsF[rr * 16 + kq + (rr >> 3)];
                unsigned long long sax, say;
                asm("mov.b64 %0, {%1,%1};" : "=l"(sax) : "f"(a.x));
                asm("mov.b64 %0, {%1,%1};" : "=l"(say) : "f"(a.y));
                #pragma unroll
                for (int i = 0; i < 4; i++) {
                    // acc = (out.x, out.y); out += a * conj(b)
                    asm("fma.rn.f32x2 %0, %1, %2, %0;" : "+l"(acc[j][i])
                        : "l"(pb1[i]), "l"(sax));
                    asm("fma.rn.f32x2 %0, %1, %2, %0;" : "+l"(acc[j][i])
                        : "l"(pb2[i]), "l"(say));
                }
            }
        }

        if (kg < KEEP) {
            #pragma unroll
            for (int j = 0; j < 4; j++)
                #pragma unroll
                for (int i = 0; i < 4; i++) {
                    float2 o;
                    asm("mov.b64 {%0,%1}, %2;" : "=f"(o.x), "=f"(o.y)
                        : "l"(acc[j][i]));
                    stc(g_So + (size_t)((nb + j) * 16 + fb + i) * KEEP + kg, o);
                }
        }
    }
}

// ============================================================================
extern "C" void kernel_launch(void* const* d_in, const int* in_sizes, int n_in,
                              void* d_out, int out_size) {
    const float2* x    = (const float2*)d_in[0];
    const float2* w    = (const float2*)d_in[1];
    const float*  bias = (const float*)d_in[2];
    float* out = (float*)d_out;

    k_init_tw<<<(M_FFT + 255) / 256, 256>>>();

    // forward: pass1 (x rows + w rows in one launch), pass2
    { dim3 g(16, NROWS_F); k_pass1<1><<<g, 256>>>(x, w); }
    { dim3 g(16, NROWS_F); k_pass2<0><<<g, 256>>>(nullptr, nullptr); }

    // pointwise contraction over c (Hermitian unpack fused into loads)
    k_einsum<<<(KEEP + KT - 1) / KT, 256>>>();

    // inverse: pass1 with fused inverse-pack, pass2 with fused depack+bias
    { dim3 g(16, NROWS_O); k_pass1<0><<<g, 256>>>(nullptr, nullptr); }
    { dim3 g(16, NROWS_O); k_pass2<1><<<g, 256>>>(out, bias); }
}

// round 11
// speedup vs baseline: 4.4916x; 1.0547x over previous
#include <cuda_runtime.h>
#include <cuda_fp16.h>

// ============================================================================
// Conv1Dfft via packed-real four-step FFT (M = 65536 = 256 x 256),
// register 16x16 FFT, fp16 global + fp16 smem intermediates, f32x2 math,
// register-tiled einsum, specialized inverse unpack + delta-row W fast path.
// ============================================================================

#define M_FFT   65536
#define KEEP    32769          // bins 0..32768 kept (== M/2+1)
#define NROWS_X 256            // 32 n * 8 c
#define NROWS_W 128            // 16 f * 8 c
#define NROWS_F 384
#define NROWS_O 512            // 32 n * 16 f
#define OUT_W   65409

// ---------------- scratch (device globals; allocation-free) ----------------
__device__ __half2 g_A[(size_t)NROWS_F * M_FFT];   // fwd pass2 out (spectra Z)
__device__ __half2 g_B[(size_t)NROWS_O * M_FFT];   // pass1 out (both directions)
__device__ __half2 g_So[(size_t)NROWS_O * KEEP];   // product spectra
__device__ float2 g_twM[M_FFT];                    // e^{-2pi i j / 65536}
__device__ float2 g_tw2M[M_FFT];                   // e^{-2pi i j / 131072}

// ---------------- packed f32x2 complex helpers -----------------------------
static __device__ __forceinline__ float2 padd(float2 a, float2 b) {
    unsigned long long ua, ub, ur;
    asm("mov.b64 %0, {%1,%2};" : "=l"(ua) : "f"(a.x), "f"(a.y));
    asm("mov.b64 %0, {%1,%2};" : "=l"(ub) : "f"(b.x), "f"(b.y));
    asm("add.rn.f32x2 %0, %1, %2;" : "=l"(ur) : "l"(ua), "l"(ub));
    float2 o;
    asm("mov.b64 {%0,%1}, %2;" : "=f"(o.x), "=f"(o.y) : "l"(ur));
    return o;
}
static __device__ __forceinline__ float2 psub(float2 a, float2 b) {
    unsigned long long ua, ub, ur;
    const unsigned long long NEG1 = 0xBF800000BF800000ULL;  // (-1.f, -1.f)
    asm("mov.b64 %0, {%1,%2};" : "=l"(ua) : "f"(a.x), "f"(a.y));
    asm("mov.b64 %0, {%1,%2};" : "=l"(ub) : "f"(b.x), "f"(b.y));
    asm("fma.rn.f32x2 %0, %1, %2, %3;" : "=l"(ur) : "l"(ub), "l"(NEG1), "l"(ua));
    float2 o;
    asm("mov.b64 {%0,%1}, %2;" : "=f"(o.x), "=f"(o.y) : "l"(ur));
    return o;
}
static __device__ __forceinline__ float2 cmul(float2 a, float2 b) {
    return make_float2(fmaf(a.x, b.x, -(a.y * b.y)),
                       fmaf(a.x, b.y,   a.y * b.x));
}
static __device__ __forceinline__ float2 ldc(const __half2* p) {
    return __half22float2(*p);
}
static __device__ __forceinline__ void stc(__half2* p, float2 v) {
    *p = __float22half2_rn(v);
}

// ---------------- twiddle tables (fp32 sincospif, exact args) --------------
__global__ void k_init_tw() {
    int i = blockIdx.x * blockDim.x + threadIdx.x;
    if (i < M_FFT) {
        float s, c;
        sincospif(-(float)i / 32768.0f, &s, &c);
        g_twM[i] = make_float2(c, s);
        sincospif(-(float)i / 65536.0f, &s, &c);
        g_tw2M[i] = make_float2(c, s);
    }
}

// ---------------- 4-pt DFT on packed complex -------------------------------
static __device__ __forceinline__ void dft4(float2 x0, float2 x1, float2 x2,
                                            float2 x3, float2& y0, float2& y1,
                                            float2& y2, float2& y3) {
    float2 s0 = padd(x0, x2);
    float2 d0 = psub(x0, x2);
    float2 s1 = padd(x1, x3);
    float2 d1 = psub(x1, x3);
    y0 = padd(s0, s1);
    y2 = psub(s0, s1);
    float2 sw = make_float2(d1.y, -d1.x);   // -i*d1
    y1 = padd(d0, sw);
    y3 = psub(d0, sw);
}

// ---------------- 16-pt DFT in registers (radix-4 x radix-4) ---------------
__device__ __forceinline__ void fft16(float2 r[16]) {
    const float C1 = 0.9238795325112867f;
    const float S1 = 0.3826834323650898f;
    const float R2 = 0.7071067811865476f;
    float2 t[16];
    {
        float2 y0, y1, y2, y3;
        dft4(r[0], r[4], r[8], r[12], y0, y1, y2, y3);
        t[0] = y0; t[4] = y1; t[8] = y2; t[12] = y3;
    }
    {
        float2 y0, y1, y2, y3;
        dft4(r[1], r[5], r[9], r[13], y0, y1, y2, y3);
        t[1]  = y0;
        t[5]  = cmul(y1, make_float2( C1, -S1));
        t[9]  = cmul(y2, make_float2( R2, -R2));
        t[13] = cmul(y3, make_float2( S1, -C1));
    }
    {
        float2 y0, y1, y2, y3;
        dft4(r[2], r[6], r[10], r[14], y0, y1, y2, y3);
        t[2]  = y0;
        t[6]  = cmul(y1, make_float2( R2, -R2));
        t[10] = make_float2( y2.y, -y2.x);
        t[14] = cmul(y3, make_float2(-R2, -R2));
    }
    {
        float2 y0, y1, y2, y3;
        dft4(r[3], r[7], r[11], r[15], y0, y1, y2, y3);
        t[3]  = y0;
        t[7]  = cmul(y1, make_float2( S1, -C1));
        t[11] = cmul(y2, make_float2(-R2, -R2));
        t[15] = cmul(y3, make_float2(-C1,  S1));
    }
    #pragma unroll
    for (int p1 = 0; p1 < 4; p1++) {
        float2 y0, y1, y2, y3;
        dft4(t[4 * p1], t[4 * p1 + 1], t[4 * p1 + 2], t[4 * p1 + 3],
             y0, y1, y2, y3);
        r[p1] = y0; r[4 + p1] = y1; r[8 + p1] = y2; r[12 + p1] = y3;
    }
}

// pad-17 smem slot for pass-kernel tiles
#define SMI(u, c) ((u) * 17 + (c))

// ---------------- pass 1: 256-pt FFT over t1 + inter twiddle ---------------
// FWD=1: rows [0,256) from x, rows [256,384) from w.  FWD=0: inverse from g_So.
template <int FWD>
__global__ __launch_bounds__(256) void k_pass1(const float2* __restrict__ x,
                                               const float2* __restrict__ w) {
    __shared__ __half2 sm[4352];
    __shared__ float2 tw256[256];
    int tid = threadIdx.x;
    int c = tid & 15, s = tid >> 4;
    int t2 = blockIdx.x * 16 + c;
    int row = blockIdx.y;

    // W fast path: only t1=0 nonzero -> FFT over t1 is constant in k1:
    //   dst[k1*256 + t2] = z[t2] * w_M^{k1*t2}.  No FFT, no smem, no barriers.
    // Branch is uniform per block (row = blockIdx.y).
    if (FWD && row >= NROWS_X) {
        float2 z = make_float2(0.f, 0.f);
        if (t2 < 64) z = w[(size_t)(row - NROWS_X) * 64 + t2];
        float2 cur = g_twM[(s * t2) & (M_FFT - 1)];
        float2 stp = g_twM[(t2 << 4) & (M_FFT - 1)];
        __half2* dst = g_B + (size_t)row * M_FFT;
        #pragma unroll
        for (int q = 0; q < 16; q++) {
            int k1 = q * 16 + s;
            stc(dst + k1 * 256 + t2, cmul(z, cur));
            cur = cmul(cur, stp);
        }
        return;
    }

    tw256[tid] = g_twM[tid << 8];

    float2 r[16];
    if (FWD) {
        const float2* xr = x + (size_t)row * 32768;
        #pragma unroll
        for (int a = 0; a < 16; a++)
            r[a] = (a < 8) ? xr[(a * 16 + s) * 256 + t2]
                           : make_float2(0.f, 0.f);
    } else {
        // inverse packed input from g_So (conj trick, /M).
        // lower half (a<8): k < 32768 -> mirror bin is zero.
        // upper half (a>=8): direct bin zero; mirror formula exact at k=32768.
        const __half2* sr = g_So + (size_t)row * KEEP;
        const float hinv = 0.5f / 65536.0f;
        float2 S[8];
        #pragma unroll
        for (int a = 0; a < 8; a++)
            S[a] = ldc(sr + (a * 16 + s) * 256 + t2);
        #pragma unroll
        for (int a = 0; a < 8; a++) {
            int k = (a * 16 + s) * 256 + t2;
            float2 T = g_tw2M[k];                 // Tc = (T.x, -T.y)
            float Ox = fmaf(T.x, S[a].x,  T.y * S[a].y);
            float Oy = fmaf(T.x, S[a].y, -(T.y * S[a].x));
            r[a] = make_float2((S[a].x - Oy) * hinv, -(S[a].y + Ox) * hinv);
        }
        #pragma unroll
        for (int a = 8; a < 16; a++)
            S[a - 8] = ldc(sr + (M_FFT - ((a * 16 + s) * 256 + t2)));
        #pragma unroll
        for (int a = 8; a < 16; a++) {
            int k = (a * 16 + s) * 256 + t2;
            float2 Sm = S[a - 8];
            float2 T = g_tw2M[k];
            float Ox = fmaf(-T.x, Sm.x,  T.y * Sm.y);
            float Oy = fmaf( T.x, Sm.y,  T.y * Sm.x);
            r[a] = make_float2((Sm.x - Oy) * hinv, (Sm.y - Ox) * hinv);
        }
    }
    __syncthreads();

    fft16(r);
    #pragma unroll
    for (int p = 0; p < 16; p++)
        stc(&sm[SMI(p * 16 + s, c)], cmul(r[p], tw256[s * p]));
    __syncthreads();
    #pragma unroll
    for (int b = 0; b < 16; b++)
        r[b] = ldc(&sm[SMI(s * 16 + b, c)]);
    fft16(r);                                // r[q] = X[16q + s]  (k1)

    float2 cur = g_twM[(s * t2) & (M_FFT - 1)];
    float2 stp = g_twM[(t2 << 4) & (M_FFT - 1)];
    __half2* dst = g_B + (size_t)row * M_FFT;
    #pragma unroll
    for (int q = 0; q < 16; q++) {
        int k1 = q * 16 + s;
        stc(dst + k1 * 256 + t2, cmul(r[q], cur));
        cur = cmul(cur, stp);
    }
}

// ---------------- pass 2: 256-pt FFT over t2, natural-order output ---------
template <int FINAL>
__global__ __launch_bounds__(256) void k_pass2(float* __restrict__ out,
                                               const float* __restrict__ bias) {
    __shared__ __half2 sm[4352];
    __shared__ float2 tw256[256];
    int tid = threadIdx.x;
    int c = tid & 15, s = tid >> 4;
    int row = blockIdx.y;
    int k1b = blockIdx.x * 16;
    tw256[tid] = g_twM[tid << 8];

    // coalesced staging: raw half2 copy (no conversion, no extra rounding)
    const __half2* src = g_B + (size_t)row * M_FFT + (size_t)k1b * 256;
    #pragma unroll
    for (int it = 0; it < 16; it++)
        sm[SMI(tid, it)] = src[it * 256 + tid];
    __syncthreads();

    float2 r[16];
    #pragma unroll
    for (int a = 0; a < 16; a++)
        r[a] = ldc(&sm[SMI(a * 16 + s, c)]);
    fft16(r);
    __syncthreads();
    #pragma unroll
    for (int p = 0; p < 16; p++)
        stc(&sm[SMI(p * 16 + s, c)], cmul(r[p], tw256[s * p]));
    __syncthreads();
    #pragma unroll
    for (int b = 0; b < 16; b++)
        r[b] = ldc(&sm[SMI(s * 16 + b, c)]);
    fft16(r);                                // r[q] = X[16q + s]  (k2)

    if (!FINAL) {
        __half2* dst = g_A + (size_t)row * M_FFT;
        #pragma unroll
        for (int q = 0; q < 16; q++)
            stc(dst + (q * 16 + s) * 256 + k1b + c, r[q]);
    } else {
        float bv = bias[row & 15];
        float* orow = out + (size_t)row * OUT_W;
        #pragma unroll
        for (int q = 0; q < 16; q++) {
            int m = (q * 16 + s) * 256 + k1b + c;   // packed time index
            int t = 2 * m;
            // scalar stores: row base is only 4B-aligned (OUT_W odd)
            if (t < OUT_W)     orow[t]     =  r[q].x + bv;
            if (t + 1 < OUT_W) orow[t + 1] = -r[q].y + bv;
        }
    }
}

// ---------------- einsum over c: 4n x 4f register tile, packed FMA ---------
// KT=16 bins/block; prefetched global loads; two sequential k-passes.
#define KT 16
__global__ __launch_bounds__(256) void k_einsum() {
    __shared__ float2 XsF[NROWS_X * KT + 64];    // skewed: slot=16r+kq+(r>>3)
    __shared__ float2 Ws[NROWS_W][KT];
    int k0 = blockIdx.x * KT;
    int tid = threadIdx.x;

    // load + Hermitian unpack: prefetch batches of 12 (zk, zm) pairs
    #pragma unroll
    for (int hb = 0; hb < 2; hb++) {
        __half2 bk[12], bm[12];
        #pragma unroll
        for (int ii = 0; ii < 12; ii++) {
            int idx = (hb * 12 + ii) * 256 + tid;
            int r = idx >> 4, kq = idx & 15;
            int kg2 = k0 + kq;
            const __half2* zr = g_A + (size_t)r * M_FFT;
            bool ok = (kg2 < KEEP);
            bk[ii] = ok ? zr[kg2] : __float2half2_rn(0.f);
            bm[ii] = ok ? zr[(M_FFT - kg2) & (M_FFT - 1)]
                        : __float2half2_rn(0.f);
        }
        #pragma unroll
        for (int ii = 0; ii < 12; ii++) {
            int idx = (hb * 12 + ii) * 256 + tid;
            int r = idx >> 4, kq = idx & 15;
            int kg2 = k0 + kq;
            float2 zk = __half22float2(bk[ii]);
            float2 zm = __half22float2(bm[ii]);
            float2 zmc = make_float2(zm.x, -zm.y);       // conj(zm)
            float2 E2 = padd(zk, zmc);                   // 2E
            float2 D  = psub(zk, zmc);
            float2 TD = cmul(g_tw2M[kg2], D);
            float2 S  = padd(E2, make_float2(TD.y, -TD.x));
            float2 X  = make_float2(0.5f * S.x, 0.5f * S.y);
            if (r < NROWS_X) XsF[r * 16 + kq + (r >> 3)] = X;
            else             Ws[r - NROWS_X][kq] = X;
        }
    }
    __syncthreads();

    int kk = tid & 7;
    int nb = ((tid >> 3) & 7) * 4;    // n base (0..28)
    int fb = (tid >> 6) * 4;          // f base (0..12)

    #pragma unroll
    for (int p = 0; p < 2; p++) {
        int kq = kk + 8 * p;
        int kg = k0 + kq;

        unsigned long long acc[4][4];
        #pragma unroll
        for (int j = 0; j < 4; j++)
            #pragma unroll
            for (int i = 0; i < 4; i++) acc[j][i] = 0ULL;

        #pragma unroll
        for (int cc = 0; cc < 8; cc++) {
            // pack 4 W values: pb1=(b.x,-b.y), pb2=(b.y,b.x)
            unsigned long long pb1[4], pb2[4];
            #pragma unroll
            for (int i = 0; i < 4; i++) {
                float2 b = Ws[(fb + i) * 8 + cc][kq];
                float nby = -b.y;
                asm("mov.b64 %0, {%1,%2};" : "=l"(pb1[i]) : "f"(b.x), "f"(nby));
                asm("mov.b64 %0, {%1,%2};" : "=l"(pb2[i]) : "f"(b.y), "f"(b.x));
            }
            #pragma unroll
            for (int j = 0; j < 4; j++) {
                int rr = (nb + j) * 8 + cc;
                float2 a = XsF[rr * 16 + kq + (rr >> 3)];
                unsigned long long sax, say;
                asm("mov.b64 %0, {%1,%1};" : "=l"(sax) : "f"(a.x));
                asm("mov.b64 %0, {%1,%1};" : "=l"(say) : "f"(a.y));
                #pragma unroll
                for (int i = 0; i < 4; i++) {
                    // acc = (out.x, out.y); out += a * conj(b)
                    asm("fma.rn.f32x2 %0, %1, %2, %0;" : "+l"(acc[j][i])
                        : "l"(pb1[i]), "l"(sax));
                    asm("fma.rn.f32x2 %0, %1, %2, %0;" : "+l"(acc[j][i])
                        : "l"(pb2[i]), "l"(say));
                }
            }
        }

        if (kg < KEEP) {
            #pragma unroll
            for (int j = 0; j < 4; j++)
                #pragma unroll
                for (int i = 0; i < 4; i++) {
                    float2 o;
                    asm("mov.b64 {%0,%1}, %2;" : "=f"(o.x), "=f"(o.y)
                        : "l"(acc[j][i]));
                    stc(g_So + (size_t)((nb + j) * 16 + fb + i) * KEEP + kg, o);
                }
        }
    }
}

// ============================================================================
extern "C" void kernel_launch(void* const* d_in, const int* in_sizes, int n_in,
                              void* d_out, int out_size) {
    const float2* x    = (const float2*)d_in[0];
    const float2* w    = (const float2*)d_in[1];
    const float*  bias = (const float*)d_in[2];
    float* out = (float*)d_out;

    k_init_tw<<<(M_FFT + 255) / 256, 256>>>();

    // forward: pass1 (x rows + delta-fast-path w rows), pass2
    { dim3 g(16, NROWS_F); k_pass1<1><<<g, 256>>>(x, w); }
    { dim3 g(16, NROWS_F); k_pass2<0><<<g, 256>>>(nullptr, nullptr); }

    // pointwise contraction over c (Hermitian unpack fused into loads)
    k_einsum<<<(KEEP + KT - 1) / KT, 256>>>();

    // inverse: pass1 with fused inverse-pack, pass2 with fused depack+bias
    { dim3 g(16, NROWS_O); k_pass1<0><<<g, 256>>>(nullptr, nullptr); }
    { dim3 g(16, NROWS_O); k_pass2<1><<<g, 256>>>(out, bias); }
}